// round 10
// baseline (speedup 1.0000x reference)
#include <cuda_runtime.h>
#include <cuda_fp16.h>
#include <cstdint>

#define BSZ    16384
#define QKV_LD 768
#define NROWS  (BSZ*3)
#define LN_EPS 1e-6f
#define TEMP_INV 0.17677669529663687f
#define APAD   3072      // A layout stride; used cols = 2048+512+448 = 3008

// ---------------- scratch (static device arrays; no cudaMalloc) --------------
__device__ __align__(16) float g_q [BSZ*QKV_LD];
__device__ __align__(16) float g_k [BSZ*QKV_LD];
__device__ __align__(16) float g_v [BSZ*QKV_LD];
__device__ __align__(16) float g_fc[BSZ*QKV_LD];
__device__ __align__(16) float g_logits[BSZ*8*9];
__device__ unsigned g_minkey;

__device__ __align__(16) __half g_ah[(size_t)BSZ*APAD];
__device__ __align__(16) __half g_al[(size_t)BSZ*APAD];
__device__ __align__(16) __half g_wh[(size_t)3*256*APAD];
__device__ __align__(16) __half g_oh[(size_t)NROWS*256];
__device__ __align__(16) __half g_ol[(size_t)NROWS*256];
__device__ __align__(16) __half g_fch[256*256];

// ---------------- small helpers ----------------------------------------------
__device__ __forceinline__ unsigned f2key(float f) {
    unsigned u = __float_as_uint(f);
    return (u & 0x80000000u) ? ~u : (u | 0x80000000u);
}
__device__ __forceinline__ float key2f(unsigned k) {
    unsigned u = (k & 0x80000000u) ? (k & 0x7FFFFFFFu) : ~k;
    return __uint_as_float(u);
}
__global__ void init_min_kernel() { g_minkey = 0xFFFFFFFFu; }

__device__ __forceinline__ uint32_t su32(const void* p) {
    return (uint32_t)__cvta_generic_to_shared(p);
}
__device__ __forceinline__ void cp16(uint32_t dst, const void* src) {
    asm volatile("cp.async.cg.shared.global [%0], [%1], 16;"
                 :: "r"(dst), "l"(src) : "memory");
}
__device__ __forceinline__ void cp_commit() {
    asm volatile("cp.async.commit_group;" ::: "memory");
}
__device__ __forceinline__ void ldm_x4(uint32_t& r0, uint32_t& r1, uint32_t& r2,
                                       uint32_t& r3, uint32_t addr) {
    asm volatile("ldmatrix.sync.aligned.m8n8.x4.shared.b16 {%0,%1,%2,%3}, [%4];"
                 : "=r"(r0), "=r"(r1), "=r"(r2), "=r"(r3) : "r"(addr));
}
__device__ __forceinline__ void mma_f16(float* c, uint32_t a0, uint32_t a1,
                                        uint32_t a2, uint32_t a3,
                                        uint32_t b0, uint32_t b1) {
    asm volatile(
        "mma.sync.aligned.m16n8k16.row.col.f32.f16.f16.f32 "
        "{%0,%1,%2,%3}, {%4,%5,%6,%7}, {%8,%9}, {%0,%1,%2,%3};"
        : "+f"(c[0]), "+f"(c[1]), "+f"(c[2]), "+f"(c[3])
        : "r"(a0), "r"(a1), "r"(a2), "r"(a3), "r"(b0), "r"(b1));
}
__device__ __forceinline__ void split_f16(float v, __half& h, __half& l) {
    h = __float2half(v);
    l = __float2half(v - __half2float(h));
}

// ---------------- conversion kernels -----------------------------------------
// padded segments: [0,2048) <- X[0,2000); [2048,2560) <- X[2000,2500); [2560,3008) <- X[2500,2900)
__global__ void __launch_bounds__(256) conv_x_kernel(const float* __restrict__ X)
{
    int col2 = (blockIdx.x * 256 + threadIdx.x) * 2;
    int row  = blockIdx.y;
    __half h[2], l[2];
#pragma unroll
    for (int e = 0; e < 2; e++) {
        int col = col2 + e;
        float x = 0.f;
        if (col < 2048)      { if (col < 2000) x = X[(size_t)row*2900 + col]; }
        else if (col < 2560) { int c = col-2048; if (c < 500) x = X[(size_t)row*2900 + 2000 + c]; }
        else                 { int c = col-2560; if (c < 400) x = X[(size_t)row*2900 + 2500 + c]; }
        split_f16(x, h[e], l[e]);
    }
    __half2 hh; hh.x = h[0]; hh.y = h[1];
    __half2 ll; ll.x = l[0]; ll.y = l[1];
    *(__half2*)&g_ah[(size_t)row*APAD + col2] = hh;
    *(__half2*)&g_al[(size_t)row*APAD + col2] = ll;
}

struct W9 { const float* w[9]; };
__global__ void __launch_bounds__(256) conv_w_kernel(W9 ws)
{
    const int Km[3]   = {2000, 500, 400};
    const int Kp[3]   = {2048, 512, 448};
    const int colA[3] = {0, 2048, 2560};
    int z = blockIdx.z, t = z / 3, m = z - t * 3;
    int idx = (blockIdx.x * 256 + threadIdx.x) * 2;
    if (idx >= 256 * Kp[m]) return;
    int n  = idx / Kp[m];
    int kp = idx - n * Kp[m];
    const float* W = ws.w[z];
    float x0 = (kp     < Km[m]) ? W[(size_t)kp*256 + n]     : 0.f;
    float x1 = (kp + 1 < Km[m]) ? W[(size_t)(kp+1)*256 + n] : 0.f;
    __half2 hh; hh.x = __float2half(x0); hh.y = __float2half(x1);
    size_t o = (size_t)t*256*APAD + (size_t)n*APAD + colA[m] + kp;
    *(__half2*)&g_wh[o] = hh;
}

__global__ void __launch_bounds__(256) conv_fcw_kernel(const float* __restrict__ fcw)
{
    int idx = (blockIdx.x * 256 + threadIdx.x) * 2;
    int n = idx >> 8, k = idx & 255;
    __half2 hh;
    hh.x = __float2half(fcw[(size_t)k*256 + n]);
    hh.y = __float2half(fcw[(size_t)(k+1)*256 + n]);
    *(__half2*)&g_fch[n*256 + k] = hh;
}

// ---------------- mma.sync split-fp16 GEMM -------------------------------------
// CTA: 128 threads, 4 warps (2x2), CTA tile 128x128, warp tile 64x64.
// C[M,128-col-tile] = A[M,K] @ B[256,K]-rows + bias
// nprod=2: pass1 Ah, pass2 Al;  nprod=1: Ah only (logits path)
struct GP {
    const __half *Ah, *Al, *B;
    int ldA, ldB, colA, colB, Kp, nprod;
    const float* bias;
    float* C; int ldc;
};

// stage: A 128x144B + B 128x144B  (K-chunk 64, 144B padded rows); 3 stages
#define SOFF_B 18432
#define SSTG   36864
#define NSTAGE 3
#define SMEM_GEMM (NSTAGE*SSTG)   // 110592 -> 2 CTAs/SM (216KB)

__device__ __forceinline__ void gemm_body(const GP p)
{
    extern __shared__ __align__(16) char dsm[];
    const int tid  = threadIdx.x;
    const int lane = tid & 31, wid = tid >> 5;
    const int wm = wid >> 1, wn = wid & 1;            // 2x2 warp grid
    const int row0 = blockIdx.y * 128, col0 = blockIdx.x * 128;
    const uint32_t sbase = su32(dsm);

    const int ck = p.Kp >> 6;          // K=64 chunks per segment
    const int nchunk = p.nprod * ck;

    auto load_chunk = [&](int c, int buf) {
        int seg = (c >= ck);
        int kc  = seg ? c - ck : c;
        const __half* A  = seg ? p.Al : p.Ah;
        const __half* As = A + (size_t)row0 * p.ldA + p.colA + kc * 64;
        const __half* Bs = p.B + (size_t)col0 * p.ldB + p.colB + kc * 64;
        uint32_t Sd = sbase + buf * SSTG;
#pragma unroll
        for (int i = 0; i < 8; i++) {
            int id = i * 128 + tid, r = id >> 3, kg = id & 7;
            cp16(Sd + r * 144 + kg * 16, As + (size_t)r * p.ldA + kg * 8);
            cp16(Sd + SOFF_B + r * 144 + kg * 16, Bs + (size_t)r * p.ldB + kg * 8);
        }
    };

    float acc[4][8][4];
#pragma unroll
    for (int i = 0; i < 4; i++)
#pragma unroll
        for (int j = 0; j < 8; j++)
#pragma unroll
            for (int r = 0; r < 4; r++) acc[i][j][r] = 0.f;

    load_chunk(0, 0); cp_commit();

    // per-lane ldmatrix byte offsets (144B smem row stride)
    const uint32_t a_off = (uint32_t)((wm * 64 + (lane & 15)) * 144 + ((lane >> 4) << 4));
    const uint32_t b_off = (uint32_t)((wn * 64 + (lane & 7) + ((lane & 16) >> 1)) * 144
                                      + ((lane & 8) << 1));

    int bufc = 0;                       // buffer holding chunk c
    for (int c = 0; c < nchunk; c++) {
        // issue chunk c+1 into buffer (c+1)%3; its previous readers were chunk
        // c-2, fenced by iteration c-1's __syncthreads -> WAR-safe.
        int bnew = bufc + 1; if (bnew == NSTAGE) bnew = 0;
        if (c + 1 < nchunk) {
            load_chunk(c + 1, bnew); cp_commit();
            asm volatile("cp.async.wait_group 1;" ::: "memory");
        } else {
            asm volatile("cp.async.wait_group 0;" ::: "memory");
        }
        __syncthreads();

        const uint32_t Sd = sbase + bufc * SSTG;
        const uint32_t Ab = Sd + a_off;
        const uint32_t Bb = Sd + SOFF_B + b_off;
#pragma unroll
        for (int kstep = 0; kstep < 4; kstep++) {
            const uint32_t kk = kstep * 32;
            uint32_t a[4][4], b[4][4];
#pragma unroll
            for (int mt = 0; mt < 4; mt++)
                ldm_x4(a[mt][0], a[mt][1], a[mt][2], a[mt][3],
                       Ab + mt * (16 * 144) + kk);
#pragma unroll
            for (int ng = 0; ng < 4; ng++)
                ldm_x4(b[ng][0], b[ng][1], b[ng][2], b[ng][3],
                       Bb + ng * (16 * 144) + kk);
#pragma unroll
            for (int mt = 0; mt < 4; mt++)
#pragma unroll
                for (int nt = 0; nt < 8; nt++)
                    mma_f16(acc[mt][nt],
                            a[mt][0], a[mt][1], a[mt][2], a[mt][3],
                            b[nt >> 1][(nt & 1) * 2], b[nt >> 1][(nt & 1) * 2 + 1]);
        }
        bufc = bnew;
    }

    // epilogue
    const int grp = lane >> 2, tig = lane & 3;
#pragma unroll
    for (int mt = 0; mt < 4; mt++) {
        int r = row0 + wm * 64 + mt * 16 + grp;
#pragma unroll
        for (int nt = 0; nt < 8; nt++) {
            int col = col0 + wn * 64 + nt * 8 + tig * 2;
            float b0 = p.bias[col], b1 = p.bias[col + 1];
            float2 lo, hi;
            lo.x = acc[mt][nt][0] + b0; lo.y = acc[mt][nt][1] + b1;
            hi.x = acc[mt][nt][2] + b0; hi.y = acc[mt][nt][3] + b1;
            *(float2*)(p.C + (size_t)r * p.ldc + col) = lo;
            *(float2*)(p.C + (size_t)(r + 8) * p.ldc + col) = hi;
        }
    }
}

struct B9 { const float* b[9]; };

// z = m*3 + t  (q/k/v of same modality adjacent: A stays L2-hot)
// Q,K: single product (logits are L1-normalized + softmaxed -> tolerant)
// V: full 2-product split (direct linear path to output)
__global__ void __launch_bounds__(128, 2) qkv_gemm_kernel(B9 biases)
{
    const int colA[3] = {0, 2048, 2560};
    const int Kp[3]   = {2048, 512, 448};
    int z = blockIdx.z, m = z / 3, t = z - m * 3;
    GP p;
    p.Ah = g_ah; p.Al = g_al; p.ldA = APAD; p.colA = colA[m];
    p.B  = g_wh + (size_t)t * 256 * APAD;
    p.ldB = APAD; p.colB = colA[m];
    p.Kp = Kp[m];
    p.nprod = (t == 2) ? 2 : 1;
    p.bias = biases.b[t * 3 + m];
    p.C = ((t == 0) ? g_q : (t == 1) ? g_k : g_v) + m * 256;
    p.ldc = QKV_LD;
    gemm_body(p);
}

__global__ void __launch_bounds__(128, 2) fc_gemm_kernel(const float* fc_b)
{
    GP p;
    p.Ah = g_oh; p.Al = g_ol; p.ldA = 256; p.colA = 0;
    p.B  = g_fch; p.ldB = 256; p.colB = 0;
    p.Kp = 256; p.nprod = 2;
    p.bias = fc_b; p.C = g_fc; p.ldc = 256;
    gemm_body(p);
}

// ------------- attention logits + global min ---------------------------------
__global__ void __launch_bounds__(256) attn_logits_kernel()
{
    int t  = blockIdx.x * blockDim.x + threadIdx.x;
    int bs = t >> 3, h = t & 7;
    const float4* qb = (const float4*)(g_q + bs * QKV_LD + h * 32);
    const float4* kb = (const float4*)(g_k + bs * QKV_LD + h * 32);

    float4 kr[3][8];
#pragma unroll
    for (int n = 0; n < 3; n++)
#pragma unroll
        for (int j = 0; j < 8; j++) kr[n][j] = kb[n * 64 + j];

    float lmin = 3.4e38f;
#pragma unroll
    for (int m = 0; m < 3; m++) {
        float4 qv[8];
#pragma unroll
        for (int j = 0; j < 8; j++) qv[j] = qb[m * 64 + j];
#pragma unroll
        for (int n = 0; n < 3; n++) {
            float s = 0.f;
#pragma unroll
            for (int j = 0; j < 8; j++) {
                s = fmaf(qv[j].x, kr[n][j].x, s);
                s = fmaf(qv[j].y, kr[n][j].y, s);
                s = fmaf(qv[j].z, kr[n][j].z, s);
                s = fmaf(qv[j].w, kr[n][j].w, s);
            }
            s *= TEMP_INV;
            g_logits[t * 9 + m * 3 + n] = s;
            lmin = fminf(lmin, s);
        }
    }
#pragma unroll
    for (int off = 16; off; off >>= 1)
        lmin = fminf(lmin, __shfl_xor_sync(0xFFFFFFFFu, lmin, off));
    if ((threadIdx.x & 31) == 0) atomicMin(&g_minkey, f2key(lmin));
}

// ------------- scale / L1 / softmax / PV -> fp16 hi/lo o ----------------------
__global__ void __launch_bounds__(256) attn_softmax_o_kernel()
{
    int t  = blockIdx.x * blockDim.x + threadIdx.x;
    int bs = t >> 3, h = t & 7;
    float inv = 1.0f / fabsf(key2f(g_minkey));

    const float* lg = g_logits + t * 9;
    const float4* vb = (const float4*)(g_v + bs * QKV_LD + h * 32);
    size_t obase = (size_t)bs * QKV_LD + h * 32;

#pragma unroll
    for (int m = 0; m < 3; m++) {
        float r0 = lg[m*3+0]*inv, r1 = lg[m*3+1]*inv, r2 = lg[m*3+2]*inv;
        float l1 = fmaxf(fabsf(r0) + fabsf(r1) + fabsf(r2), 1e-12f);
        r0 /= l1; r1 /= l1; r2 /= l1;
        float mx = fmaxf(r0, fmaxf(r1, r2));
        float e0 = expf(r0-mx), e1 = expf(r1-mx), e2 = expf(r2-mx);
        float es = e0 + e1 + e2;
        float p0 = e0/es, p1 = e1/es, p2 = e2/es;

        __half2* oh2 = (__half2*)&g_oh[obase + m * 256];
        __half2* ol2 = (__half2*)&g_ol[obase + m * 256];
#pragma unroll
        for (int j = 0; j < 8; j++) {
            float4 v0 = vb[j], v1 = vb[64+j], v2 = vb[128+j];
            float r[4];
            r[0] = p0*v0.x + p1*v1.x + p2*v2.x;
            r[1] = p0*v0.y + p1*v1.y + p2*v2.y;
            r[2] = p0*v0.z + p1*v1.z + p2*v2.z;
            r[3] = p0*v0.w + p1*v1.w + p2*v2.w;
            __half hh[4], ll[4];
#pragma unroll
            for (int e = 0; e < 4; e++) split_f16(r[e], hh[e], ll[e]);
            __half2 h01; h01.x = hh[0]; h01.y = hh[1];
            __half2 h23; h23.x = hh[2]; h23.y = hh[3];
            __half2 l01; l01.x = ll[0]; l01.y = ll[1];
            __half2 l23; l23.x = ll[2]; l23.y = ll[3];
            oh2[j*2]   = h01; oh2[j*2+1] = h23;
            ol2[j*2]   = l01; ol2[j*2+1] = l23;
        }
    }
}

// ------------- fused residual + layernorm + out GEMM --------------------------
__global__ void __launch_bounds__(256) ln_out_kernel(
    const float* __restrict__ ln_g, const float* __restrict__ ln_b,
    const float* __restrict__ out_w, const float* __restrict__ out_b,
    float* __restrict__ out)
{
    __shared__ float red[8][8];
    __shared__ float bcast[8];

    int s = blockIdx.x, tid = threadIdx.x;
    int lane = tid & 31, wid = tid >> 5;

    float x[3];
#pragma unroll
    for (int m = 0; m < 3; m++) {
        size_t r = (size_t)(s * 3 + m) * 256 + tid;
        x[m] = g_fc[r] + g_v[r];
    }

    float v6[6] = {x[0], x[1], x[2], x[0]*x[0], x[1]*x[1], x[2]*x[2]};
#pragma unroll
    for (int off = 16; off; off >>= 1)
#pragma unroll
        for (int i = 0; i < 6; i++)
            v6[i] += __shfl_xor_sync(0xFFFFFFFFu, v6[i], off);
    if (lane < 6) red[wid][lane] = v6[lane];
    __syncthreads();
    if (wid == 0) {
#pragma unroll
        for (int i = 0; i < 6; i++) {
            float t = (lane < 8) ? red[lane][i] : 0.f;
#pragma unroll
            for (int off = 4; off; off >>= 1)
                t += __shfl_xor_sync(0xFFFFFFFFu, t, off);
            if (lane == 0) bcast[i] = t;
        }
    }
    __syncthreads();

    float gg = ln_g[tid], bb = ln_b[tid];
    float acc[5] = {0.f, 0.f, 0.f, 0.f, 0.f};
#pragma unroll
    for (int m = 0; m < 3; m++) {
        float mu  = bcast[m] * (1.0f / 256.0f);
        float var = bcast[m + 3] * (1.0f / 256.0f) - mu * mu;
        float rstd = rsqrtf(var + LN_EPS);
        float xn = (x[m] - mu) * rstd * gg + bb;
        const float* wrow = out_w + (size_t)(m * 256 + tid) * 5;
#pragma unroll
        for (int c = 0; c < 5; c++) acc[c] = fmaf(xn, wrow[c], acc[c]);
    }
#pragma unroll
    for (int off = 16; off; off >>= 1)
#pragma unroll
        for (int c = 0; c < 5; c++)
            acc[c] += __shfl_xor_sync(0xFFFFFFFFu, acc[c], off);
    if (lane < 5) red[wid][lane] = acc[lane];
    __syncthreads();
    if (wid == 0 && lane < 5) {
        float t = 0.f;
#pragma unroll
        for (int w = 0; w < 8; w++) t += red[w][lane];
        out[s * 5 + lane] = t + out_b[lane];
    }
}

// ==============================================================================
extern "C" void kernel_launch(void* const* d_in, const int* in_sizes, int n_in,
                              void* d_out, int out_size)
{
    const float* X = (const float*)d_in[0];
    W9 ws; B9 bs;
    for (int t = 0; t < 3; t++)
        for (int m = 0; m < 3; m++) {
            ws.w[t*3+m] = (const float*)d_in[1 + t*6 + m*2];
            bs.b[t*3+m] = (const float*)d_in[2 + t*6 + m*2];
        }
    const float* fc_w  = (const float*)d_in[19];
    const float* fc_b  = (const float*)d_in[20];
    const float* ln_g  = (const float*)d_in[21];
    const float* ln_b  = (const float*)d_in[22];
    const float* out_w = (const float*)d_in[23];
    const float* out_b = (const float*)d_in[24];
    float* out = (float*)d_out;

    static int smem_set = 0;
    if (!smem_set) {
        cudaFuncSetAttribute(qkv_gemm_kernel, cudaFuncAttributeMaxDynamicSharedMemorySize, SMEM_GEMM);
        cudaFuncSetAttribute(fc_gemm_kernel,  cudaFuncAttributeMaxDynamicSharedMemorySize, SMEM_GEMM);
        smem_set = 1;
    }

    init_min_kernel<<<1, 1>>>();                    // idx 0
    conv_x_kernel<<<dim3(6, BSZ), 256>>>(X);        // idx 1
    conv_w_kernel<<<dim3(1024, 1, 9), 256>>>(ws);   // idx 2

    qkv_gemm_kernel<<<dim3(2, BSZ/128, 9), 128, SMEM_GEMM>>>(bs);  // idx 3 -> ncu target

    conv_fcw_kernel<<<128, 256>>>(fc_w);            // idx 4

    attn_logits_kernel<<<(BSZ*8)/256, 256>>>();
    attn_softmax_o_kernel<<<(BSZ*8)/256, 256>>>();

    fc_gemm_kernel<<<dim3(2, NROWS/128, 1), 128, SMEM_GEMM>>>(fc_b);

    ln_out_kernel<<<BSZ, 256>>>(ln_g, ln_b, out_w, out_b, out);
}

// round 11
// speedup vs baseline: 1.0760x; 1.0760x over previous
#include <cuda_runtime.h>
#include <cuda_fp16.h>
#include <cstdint>

#define BSZ    16384
#define QKV_LD 768
#define NROWS  (BSZ*3)
#define LN_EPS 1e-6f
#define TEMP_INV 0.17677669529663687f
#define APAD   3072      // A layout stride; used cols = 2048+512+448 = 3008

// ---------------- scratch (static device arrays; no cudaMalloc) --------------
__device__ __align__(16) float g_v [BSZ*QKV_LD];
__device__ __align__(16) float g_fc[BSZ*QKV_LD];
__device__ __align__(16) float g_logits[BSZ*8*9];
__device__ unsigned g_minkey;

__device__ __align__(16) __half g_qh[BSZ*QKV_LD];   // q,k in fp16 (logits-only)
__device__ __align__(16) __half g_kh[BSZ*QKV_LD];
__device__ __align__(16) __half g_ah[(size_t)BSZ*APAD];
__device__ __align__(16) __half g_al[(size_t)BSZ*APAD];
__device__ __align__(16) __half g_wh[(size_t)3*256*APAD];
__device__ __align__(16) __half g_oh[(size_t)NROWS*256];
__device__ __align__(16) __half g_ol[(size_t)NROWS*256];
__device__ __align__(16) __half g_fch[256*256];

// ---------------- small helpers ----------------------------------------------
__device__ __forceinline__ unsigned f2key(float f) {
    unsigned u = __float_as_uint(f);
    return (u & 0x80000000u) ? ~u : (u | 0x80000000u);
}
__device__ __forceinline__ float key2f(unsigned k) {
    unsigned u = (k & 0x80000000u) ? (k & 0x7FFFFFFFu) : ~k;
    return __uint_as_float(u);
}
__global__ void init_min_kernel() { g_minkey = 0xFFFFFFFFu; }

__device__ __forceinline__ uint32_t su32(const void* p) {
    return (uint32_t)__cvta_generic_to_shared(p);
}
__device__ __forceinline__ void cp16(uint32_t dst, const void* src) {
    asm volatile("cp.async.cg.shared.global [%0], [%1], 16;"
                 :: "r"(dst), "l"(src) : "memory");
}
__device__ __forceinline__ void cp_commit() {
    asm volatile("cp.async.commit_group;" ::: "memory");
}
__device__ __forceinline__ void ldm_x4(uint32_t& r0, uint32_t& r1, uint32_t& r2,
                                       uint32_t& r3, uint32_t addr) {
    asm volatile("ldmatrix.sync.aligned.m8n8.x4.shared.b16 {%0,%1,%2,%3}, [%4];"
                 : "=r"(r0), "=r"(r1), "=r"(r2), "=r"(r3) : "r"(addr));
}
__device__ __forceinline__ void mma_f16(float* c, uint32_t a0, uint32_t a1,
                                        uint32_t a2, uint32_t a3,
                                        uint32_t b0, uint32_t b1) {
    asm volatile(
        "mma.sync.aligned.m16n8k16.row.col.f32.f16.f16.f32 "
        "{%0,%1,%2,%3}, {%4,%5,%6,%7}, {%8,%9}, {%0,%1,%2,%3};"
        : "+f"(c[0]), "+f"(c[1]), "+f"(c[2]), "+f"(c[3])
        : "r"(a0), "r"(a1), "r"(a2), "r"(a3), "r"(b0), "r"(b1));
}
__device__ __forceinline__ void split_f16(float v, __half& h, __half& l) {
    h = __float2half(v);
    l = __float2half(v - __half2float(h));
}
__device__ __forceinline__ float dot8(uint4 a, uint4 b) {
    const __half2* pa = (const __half2*)&a;
    const __half2* pb = (const __half2*)&b;
    float s = 0.f;
#pragma unroll
    for (int i = 0; i < 4; i++) {
        float2 fa = __half22float2(pa[i]), fb = __half22float2(pb[i]);
        s = fmaf(fa.x, fb.x, s);
        s = fmaf(fa.y, fb.y, s);
    }
    return s;
}

// ---------------- conversion kernels -----------------------------------------
// padded segments: [0,2048) <- X[0,2000); [2048,2560) <- X[2000,2500); [2560,3008) <- X[2500,2900)
__global__ void __launch_bounds__(256) conv_x_kernel(const float* __restrict__ X)
{
    int col2 = (blockIdx.x * 256 + threadIdx.x) * 2;
    int row  = blockIdx.y;
    __half h[2], l[2];
#pragma unroll
    for (int e = 0; e < 2; e++) {
        int col = col2 + e;
        float x = 0.f;
        if (col < 2048)      { if (col < 2000) x = X[(size_t)row*2900 + col]; }
        else if (col < 2560) { int c = col-2048; if (c < 500) x = X[(size_t)row*2900 + 2000 + c]; }
        else                 { int c = col-2560; if (c < 400) x = X[(size_t)row*2900 + 2500 + c]; }
        split_f16(x, h[e], l[e]);
    }
    __half2 hh; hh.x = h[0]; hh.y = h[1];
    __half2 ll; ll.x = l[0]; ll.y = l[1];
    *(__half2*)&g_ah[(size_t)row*APAD + col2] = hh;
    *(__half2*)&g_al[(size_t)row*APAD + col2] = ll;
}

struct W9 { const float* w[9]; };
__global__ void __launch_bounds__(256) conv_w_kernel(W9 ws)
{
    const int Km[3]   = {2000, 500, 400};
    const int Kp[3]   = {2048, 512, 448};
    const int colA[3] = {0, 2048, 2560};
    int z = blockIdx.z, t = z / 3, m = z - t * 3;
    int idx = (blockIdx.x * 256 + threadIdx.x) * 2;
    if (idx >= 256 * Kp[m]) return;
    int n  = idx / Kp[m];
    int kp = idx - n * Kp[m];
    const float* W = ws.w[z];
    float x0 = (kp     < Km[m]) ? W[(size_t)kp*256 + n]     : 0.f;
    float x1 = (kp + 1 < Km[m]) ? W[(size_t)(kp+1)*256 + n] : 0.f;
    __half2 hh; hh.x = __float2half(x0); hh.y = __float2half(x1);
    size_t o = (size_t)t*256*APAD + (size_t)n*APAD + colA[m] + kp;
    *(__half2*)&g_wh[o] = hh;
}

__global__ void __launch_bounds__(256) conv_fcw_kernel(const float* __restrict__ fcw)
{
    int idx = (blockIdx.x * 256 + threadIdx.x) * 2;
    int n = idx >> 8, k = idx & 255;
    __half2 hh;
    hh.x = __float2half(fcw[(size_t)k*256 + n]);
    hh.y = __float2half(fcw[(size_t)(k+1)*256 + n]);
    *(__half2*)&g_fch[n*256 + k] = hh;
}

// ---------------- mma.sync split-fp16 GEMM -------------------------------------
// R9 shape: 256 threads, 8 warps (2x4), CTA tile 128x128, warp tile 64x32.
// nprod=2: pass1 Ah, pass2 Al;  nprod=1: Ah only (logits path)
// ohalf=1: write __half output; 0: float output.
struct GP {
    const __half *Ah, *Al, *B;
    int ldA, ldB, colA, colB, Kp, nprod, ohalf;
    const float* bias;
    void* C; int ldc;
};

// stage: A 128x144B + B 128x144B  (K-chunk 64, 144B padded rows); 3 stages
#define SOFF_B 18432
#define SSTG   36864
#define NSTAGE 3
#define SMEM_GEMM (NSTAGE*SSTG)   // 110592 -> 2 CTAs/SM (216KB)

__device__ __forceinline__ void gemm_body(const GP p)
{
    extern __shared__ __align__(16) char dsm[];
    const int tid  = threadIdx.x;
    const int lane = tid & 31, wid = tid >> 5;
    const int wm = wid >> 2, wn = wid & 3;            // 2x4 warp grid
    const int row0 = blockIdx.y * 128, col0 = blockIdx.x * 128;
    const uint32_t sbase = su32(dsm);

    const int ck = p.Kp >> 6;          // K=64 chunks per segment
    const int nchunk = p.nprod * ck;

    auto load_chunk = [&](int c, int buf) {
        int seg = (c >= ck);
        int kc  = seg ? c - ck : c;
        const __half* A  = seg ? p.Al : p.Ah;
        const __half* As = A + (size_t)row0 * p.ldA + p.colA + kc * 64;
        const __half* Bs = p.B + (size_t)col0 * p.ldB + p.colB + kc * 64;
        uint32_t Sd = sbase + buf * SSTG;
#pragma unroll
        for (int i = 0; i < 4; i++) {
            int id = i * 256 + tid, r = id >> 3, kg = id & 7;
            cp16(Sd + r * 144 + kg * 16, As + (size_t)r * p.ldA + kg * 8);
            cp16(Sd + SOFF_B + r * 144 + kg * 16, Bs + (size_t)r * p.ldB + kg * 8);
        }
    };

    float acc[4][4][4];
#pragma unroll
    for (int i = 0; i < 4; i++)
#pragma unroll
        for (int j = 0; j < 4; j++)
#pragma unroll
            for (int r = 0; r < 4; r++) acc[i][j][r] = 0.f;

    load_chunk(0, 0); cp_commit();

    // per-lane ldmatrix byte offsets (144B smem row stride)
    const uint32_t a_off = (uint32_t)((wm * 64 + (lane & 15)) * 144 + ((lane >> 4) << 4));
    const uint32_t b_off = (uint32_t)((wn * 32 + (lane & 7) + ((lane & 16) >> 1)) * 144
                                      + ((lane & 8) << 1));

    int bufc = 0;                       // buffer holding chunk c
    for (int c = 0; c < nchunk; c++) {
        // issue chunk c+1 into buffer (c+1)%3; its previous readers were chunk
        // c-2, fenced by iteration c-1's __syncthreads -> WAR-safe.
        int bnew = bufc + 1; if (bnew == NSTAGE) bnew = 0;
        if (c + 1 < nchunk) {
            load_chunk(c + 1, bnew); cp_commit();
            asm volatile("cp.async.wait_group 1;" ::: "memory");
        } else {
            asm volatile("cp.async.wait_group 0;" ::: "memory");
        }
        __syncthreads();

        const uint32_t Sd = sbase + bufc * SSTG;
        const uint32_t Ab = Sd + a_off;
        const uint32_t Bb = Sd + SOFF_B + b_off;
#pragma unroll
        for (int kstep = 0; kstep < 4; kstep++) {
            const uint32_t kk = kstep * 32;
            uint32_t a[4][4], b[2][4];
#pragma unroll
            for (int mt = 0; mt < 4; mt++)
                ldm_x4(a[mt][0], a[mt][1], a[mt][2], a[mt][3],
                       Ab + mt * (16 * 144) + kk);
#pragma unroll
            for (int ng = 0; ng < 2; ng++)
                ldm_x4(b[ng][0], b[ng][1], b[ng][2], b[ng][3],
                       Bb + ng * (16 * 144) + kk);
#pragma unroll
            for (int mt = 0; mt < 4; mt++)
#pragma unroll
                for (int nt = 0; nt < 4; nt++)
                    mma_f16(acc[mt][nt],
                            a[mt][0], a[mt][1], a[mt][2], a[mt][3],
                            b[nt >> 1][(nt & 1) * 2], b[nt >> 1][(nt & 1) * 2 + 1]);
        }
        bufc = bnew;
    }

    // epilogue
    const int grp = lane >> 2, tig = lane & 3;
#pragma unroll
    for (int mt = 0; mt < 4; mt++) {
        int r = row0 + wm * 64 + mt * 16 + grp;
#pragma unroll
        for (int nt = 0; nt < 4; nt++) {
            int col = col0 + wn * 32 + nt * 8 + tig * 2;
            float b0 = p.bias[col], b1 = p.bias[col + 1];
            float v00 = acc[mt][nt][0] + b0, v01 = acc[mt][nt][1] + b1;
            float v10 = acc[mt][nt][2] + b0, v11 = acc[mt][nt][3] + b1;
            if (p.ohalf) {
                __half* C = (__half*)p.C;
                __half2 lo; lo.x = __float2half(v00); lo.y = __float2half(v01);
                __half2 hi; hi.x = __float2half(v10); hi.y = __float2half(v11);
                *(__half2*)(C + (size_t)r * p.ldc + col) = lo;
                *(__half2*)(C + (size_t)(r + 8) * p.ldc + col) = hi;
            } else {
                float* C = (float*)p.C;
                float2 lo; lo.x = v00; lo.y = v01;
                float2 hi; hi.x = v10; hi.y = v11;
                *(float2*)(C + (size_t)r * p.ldc + col) = lo;
                *(float2*)(C + (size_t)(r + 8) * p.ldc + col) = hi;
            }
        }
    }
}

struct B9 { const float* b[9]; };

// z = m*3 + t  (q/k/v of same modality adjacent: A stays L2-hot)
// Q,K: single product, fp16 output (logits path: L1-norm + softmax tolerant)
// V: full 2-product split, fp32 output (direct linear path to output)
__global__ void __launch_bounds__(256, 2) qkv_gemm_kernel(B9 biases)
{
    const int colA[3] = {0, 2048, 2560};
    const int Kp[3]   = {2048, 512, 448};
    int z = blockIdx.z, m = z / 3, t = z - m * 3;
    GP p;
    p.Ah = g_ah; p.Al = g_al; p.ldA = APAD; p.colA = colA[m];
    p.B  = g_wh + (size_t)t * 256 * APAD;
    p.ldB = APAD; p.colB = colA[m];
    p.Kp = Kp[m];
    p.nprod = (t == 2) ? 2 : 1;
    p.ohalf = (t == 2) ? 0 : 1;
    p.bias = biases.b[t * 3 + m];
    if (t == 0)      p.C = (void*)(g_qh + m * 256);
    else if (t == 1) p.C = (void*)(g_kh + m * 256);
    else             p.C = (void*)(g_v  + m * 256);
    p.ldc = QKV_LD;
    gemm_body(p);
}

__global__ void __launch_bounds__(256, 2) fc_gemm_kernel(const float* fc_b)
{
    GP p;
    p.Ah = g_oh; p.Al = g_ol; p.ldA = 256; p.colA = 0;
    p.B  = g_fch; p.ldB = 256; p.colB = 0;
    p.Kp = 256; p.nprod = 2; p.ohalf = 0;
    p.bias = fc_b; p.C = (void*)g_fc; p.ldc = 256;
    gemm_body(p);
}

// ------------- attention logits + global min (fp16 q,k) -----------------------
__global__ void __launch_bounds__(256) attn_logits_kernel()
{
    int t  = blockIdx.x * blockDim.x + threadIdx.x;
    int bs = t >> 3, h = t & 7;
    // head block: offset bs*768 + n*256 + h*32 halves = (bs*96 + n*32 + h*4) uint4
    const uint4* qb = (const uint4*)g_qh + (size_t)bs * 96 + h * 4;
    const uint4* kb = (const uint4*)g_kh + (size_t)bs * 96 + h * 4;

    uint4 kr[3][4];
#pragma unroll
    for (int n = 0; n < 3; n++)
#pragma unroll
        for (int j = 0; j < 4; j++) kr[n][j] = kb[n * 32 + j];

    float lmin = 3.4e38f;
#pragma unroll
    for (int m = 0; m < 3; m++) {
        uint4 qv[4];
#pragma unroll
        for (int j = 0; j < 4; j++) qv[j] = qb[m * 32 + j];
#pragma unroll
        for (int n = 0; n < 3; n++) {
            float s = 0.f;
#pragma unroll
            for (int j = 0; j < 4; j++) s += dot8(qv[j], kr[n][j]);
            s *= TEMP_INV;
            g_logits[t * 9 + m * 3 + n] = s;
            lmin = fminf(lmin, s);
        }
    }
#pragma unroll
    for (int off = 16; off; off >>= 1)
        lmin = fminf(lmin, __shfl_xor_sync(0xFFFFFFFFu, lmin, off));
    if ((threadIdx.x & 31) == 0) atomicMin(&g_minkey, f2key(lmin));
}

// ------------- scale / L1 / softmax / PV -> fp16 hi/lo o ----------------------
__global__ void __launch_bounds__(256) attn_softmax_o_kernel()
{
    int t  = blockIdx.x * blockDim.x + threadIdx.x;
    int bs = t >> 3, h = t & 7;
    float inv = 1.0f / fabsf(key2f(g_minkey));

    const float* lg = g_logits + t * 9;
    const float4* vb = (const float4*)(g_v + bs * QKV_LD + h * 32);
    size_t obase = (size_t)bs * QKV_LD + h * 32;

#pragma unroll
    for (int m = 0; m < 3; m++) {
        float r0 = lg[m*3+0]*inv, r1 = lg[m*3+1]*inv, r2 = lg[m*3+2]*inv;
        float l1 = fmaxf(fabsf(r0) + fabsf(r1) + fabsf(r2), 1e-12f);
        r0 /= l1; r1 /= l1; r2 /= l1;
        float mx = fmaxf(r0, fmaxf(r1, r2));
        float e0 = expf(r0-mx), e1 = expf(r1-mx), e2 = expf(r2-mx);
        float es = e0 + e1 + e2;
        float p0 = e0/es, p1 = e1/es, p2 = e2/es;

        __half2* oh2 = (__half2*)&g_oh[obase + m * 256];
        __half2* ol2 = (__half2*)&g_ol[obase + m * 256];
#pragma unroll
        for (int j = 0; j < 8; j++) {
            float4 v0 = vb[j], v1 = vb[64+j], v2 = vb[128+j];
            float r[4];
            r[0] = p0*v0.x + p1*v1.x + p2*v2.x;
            r[1] = p0*v0.y + p1*v1.y + p2*v2.y;
            r[2] = p0*v0.z + p1*v1.z + p2*v2.z;
            r[3] = p0*v0.w + p1*v1.w + p2*v2.w;
            __half hh[4], ll[4];
#pragma unroll
            for (int e = 0; e < 4; e++) split_f16(r[e], hh[e], ll[e]);
            __half2 h01; h01.x = hh[0]; h01.y = hh[1];
            __half2 h23; h23.x = hh[2]; h23.y = hh[3];
            __half2 l01; l01.x = ll[0]; l01.y = ll[1];
            __half2 l23; l23.x = ll[2]; l23.y = ll[3];
            oh2[j*2]   = h01; oh2[j*2+1] = h23;
            ol2[j*2]   = l01; ol2[j*2+1] = l23;
        }
    }
}

// ------------- fused residual + layernorm + out GEMM --------------------------
__global__ void __launch_bounds__(256) ln_out_kernel(
    const float* __restrict__ ln_g, const float* __restrict__ ln_b,
    const float* __restrict__ out_w, const float* __restrict__ out_b,
    float* __restrict__ out)
{
    __shared__ float red[8][8];
    __shared__ float bcast[8];

    int s = blockIdx.x, tid = threadIdx.x;
    int lane = tid & 31, wid = tid >> 5;

    float x[3];
#pragma unroll
    for (int m = 0; m < 3; m++) {
        size_t r = (size_t)(s * 3 + m) * 256 + tid;
        x[m] = g_fc[r] + g_v[r];
    }

    float v6[6] = {x[0], x[1], x[2], x[0]*x[0], x[1]*x[1], x[2]*x[2]};
#pragma unroll
    for (int off = 16; off; off >>= 1)
#pragma unroll
        for (int i = 0; i < 6; i++)
            v6[i] += __shfl_xor_sync(0xFFFFFFFFu, v6[i], off);
    if (lane < 6) red[wid][lane] = v6[lane];
    __syncthreads();
    if (wid == 0) {
#pragma unroll
        for (int i = 0; i < 6; i++) {
            float t = (lane < 8) ? red[lane][i] : 0.f;
#pragma unroll
            for (int off = 4; off; off >>= 1)
                t += __shfl_xor_sync(0xFFFFFFFFu, t, off);
            if (lane == 0) bcast[i] = t;
        }
    }
    __syncthreads();

    float gg = ln_g[tid], bb = ln_b[tid];
    float acc[5] = {0.f, 0.f, 0.f, 0.f, 0.f};
#pragma unroll
    for (int m = 0; m < 3; m++) {
        float mu  = bcast[m] * (1.0f / 256.0f);
        float var = bcast[m + 3] * (1.0f / 256.0f) - mu * mu;
        float rstd = rsqrtf(var + LN_EPS);
        float xn = (x[m] - mu) * rstd * gg + bb;
        const float* wrow = out_w + (size_t)(m * 256 + tid) * 5;
#pragma unroll
        for (int c = 0; c < 5; c++) acc[c] = fmaf(xn, wrow[c], acc[c]);
    }
#pragma unroll
    for (int off = 16; off; off >>= 1)
#pragma unroll
        for (int c = 0; c < 5; c++)
            acc[c] += __shfl_xor_sync(0xFFFFFFFFu, acc[c], off);
    if (lane < 5) red[wid][lane] = acc[lane];
    __syncthreads();
    if (wid == 0 && lane < 5) {
        float t = 0.f;
#pragma unroll
        for (int w = 0; w < 8; w++) t += red[w][lane];
        out[s * 5 + lane] = t + out_b[lane];
    }
}

// ==============================================================================
extern "C" void kernel_launch(void* const* d_in, const int* in_sizes, int n_in,
                              void* d_out, int out_size)
{
    const float* X = (const float*)d_in[0];
    W9 ws; B9 bs;
    for (int t = 0; t < 3; t++)
        for (int m = 0; m < 3; m++) {
            ws.w[t*3+m] = (const float*)d_in[1 + t*6 + m*2];
            bs.b[t*3+m] = (const float*)d_in[2 + t*6 + m*2];
        }
    const float* fc_w  = (const float*)d_in[19];
    const float* fc_b  = (const float*)d_in[20];
    const float* ln_g  = (const float*)d_in[21];
    const float* ln_b  = (const float*)d_in[22];
    const float* out_w = (const float*)d_in[23];
    const float* out_b = (const float*)d_in[24];
    float* out = (float*)d_out;

    static int smem_set = 0;
    if (!smem_set) {
        cudaFuncSetAttribute(qkv_gemm_kernel, cudaFuncAttributeMaxDynamicSharedMemorySize, SMEM_GEMM);
        cudaFuncSetAttribute(fc_gemm_kernel,  cudaFuncAttributeMaxDynamicSharedMemorySize, SMEM_GEMM);
        smem_set = 1;
    }

    init_min_kernel<<<1, 1>>>();                    // idx 0
    conv_x_kernel<<<dim3(6, BSZ), 256>>>(X);        // idx 1
    conv_w_kernel<<<dim3(1024, 1, 9), 256>>>(ws);   // idx 2

    qkv_gemm_kernel<<<dim3(2, BSZ/128, 9), 256, SMEM_GEMM>>>(bs);  // idx 3 -> ncu target

    conv_fcw_kernel<<<128, 256>>>(fc_w);            // idx 4

    attn_logits_kernel<<<(BSZ*8)/256, 256>>>();
    attn_softmax_o_kernel<<<(BSZ*8)/256, 256>>>();

    fc_gemm_kernel<<<dim3(2, NROWS/128, 1), 256, SMEM_GEMM>>>(fc_b);

    ln_out_kernel<<<BSZ, 256>>>(ln_g, ln_b, out_w, out_b, out);
}

// round 12
// speedup vs baseline: 1.1223x; 1.0431x over previous
#include <cuda_runtime.h>
#include <cuda_fp16.h>
#include <cstdint>

#define BSZ    16384
#define QKV_LD 768
#define NROWS  (BSZ*3)
#define LN_EPS 1e-6f
#define TEMP_INV 0.17677669529663687f
#define APAD   3072      // A layout stride; used cols = 2048+512+448 = 3008

// ---------------- scratch (static device arrays; no cudaMalloc) --------------
__device__ __align__(16) float g_v [BSZ*QKV_LD];
__device__ __align__(16) float g_fc[BSZ*QKV_LD];
__device__ __align__(16) float g_logits[BSZ*8*9];
__device__ unsigned g_minkey;

__device__ __align__(16) __half g_qh[BSZ*QKV_LD];   // q,k in fp16 (logits-only)
__device__ __align__(16) __half g_kh[BSZ*QKV_LD];
__device__ __align__(16) __half g_ah[(size_t)BSZ*APAD];
__device__ __align__(16) __half g_al[(size_t)BSZ*APAD];
__device__ __align__(16) __half g_wh[(size_t)3*256*APAD];
__device__ __align__(16) __half g_oh[(size_t)NROWS*256];
__device__ __align__(16) __half g_fch[256*256];

// ---------------- small helpers ----------------------------------------------
__device__ __forceinline__ unsigned f2key(float f) {
    unsigned u = __float_as_uint(f);
    return (u & 0x80000000u) ? ~u : (u | 0x80000000u);
}
__device__ __forceinline__ float key2f(unsigned k) {
    unsigned u = (k & 0x80000000u) ? (k & 0x7FFFFFFFu) : ~k;
    return __uint_as_float(u);
}
__global__ void init_min_kernel() { g_minkey = 0xFFFFFFFFu; }

__device__ __forceinline__ uint32_t su32(const void* p) {
    return (uint32_t)__cvta_generic_to_shared(p);
}
__device__ __forceinline__ void cp16(uint32_t dst, const void* src) {
    asm volatile("cp.async.cg.shared.global [%0], [%1], 16;"
                 :: "r"(dst), "l"(src) : "memory");
}
__device__ __forceinline__ void cp_commit() {
    asm volatile("cp.async.commit_group;" ::: "memory");
}
__device__ __forceinline__ void ldm_x4(uint32_t& r0, uint32_t& r1, uint32_t& r2,
                                       uint32_t& r3, uint32_t addr) {
    asm volatile("ldmatrix.sync.aligned.m8n8.x4.shared.b16 {%0,%1,%2,%3}, [%4];"
                 : "=r"(r0), "=r"(r1), "=r"(r2), "=r"(r3) : "r"(addr));
}
__device__ __forceinline__ void mma_f16(float* c, uint32_t a0, uint32_t a1,
                                        uint32_t a2, uint32_t a3,
                                        uint32_t b0, uint32_t b1) {
    asm volatile(
        "mma.sync.aligned.m16n8k16.row.col.f32.f16.f16.f32 "
        "{%0,%1,%2,%3}, {%4,%5,%6,%7}, {%8,%9}, {%0,%1,%2,%3};"
        : "+f"(c[0]), "+f"(c[1]), "+f"(c[2]), "+f"(c[3])
        : "r"(a0), "r"(a1), "r"(a2), "r"(a3), "r"(b0), "r"(b1));
}
__device__ __forceinline__ void split_f16(float v, __half& h, __half& l) {
    h = __float2half(v);
    l = __float2half(v - __half2float(h));
}
__device__ __forceinline__ float dot8(uint4 a, uint4 b) {
    const __half2* pa = (const __half2*)&a;
    const __half2* pb = (const __half2*)&b;
    float s = 0.f;
#pragma unroll
    for (int i = 0; i < 4; i++) {
        float2 fa = __half22float2(pa[i]), fb = __half22float2(pb[i]);
        s = fmaf(fa.x, fb.x, s);
        s = fmaf(fa.y, fb.y, s);
    }
    return s;
}

// ---------------- conversion kernels -----------------------------------------
// padded segments: [0,2048) <- X[0,2000); [2048,2560) <- X[2000,2500); [2560,3008) <- X[2500,2900)
__global__ void __launch_bounds__(256) conv_x_kernel(const float* __restrict__ X)
{
    int col2 = (blockIdx.x * 256 + threadIdx.x) * 2;
    int row  = blockIdx.y;
    __half h[2], l[2];
#pragma unroll
    for (int e = 0; e < 2; e++) {
        int col = col2 + e;
        float x = 0.f;
        if (col < 2048)      { if (col < 2000) x = X[(size_t)row*2900 + col]; }
        else if (col < 2560) { int c = col-2048; if (c < 500) x = X[(size_t)row*2900 + 2000 + c]; }
        else                 { int c = col-2560; if (c < 400) x = X[(size_t)row*2900 + 2500 + c]; }
        split_f16(x, h[e], l[e]);
    }
    __half2 hh; hh.x = h[0]; hh.y = h[1];
    __half2 ll; ll.x = l[0]; ll.y = l[1];
    *(__half2*)&g_ah[(size_t)row*APAD + col2] = hh;
    *(__half2*)&g_al[(size_t)row*APAD + col2] = ll;
}

struct W9 { const float* w[9]; };
__global__ void __launch_bounds__(256) conv_w_kernel(W9 ws)
{
    const int Km[3]   = {2000, 500, 400};
    const int Kp[3]   = {2048, 512, 448};
    const int colA[3] = {0, 2048, 2560};
    int z = blockIdx.z, t = z / 3, m = z - t * 3;
    int idx = (blockIdx.x * 256 + threadIdx.x) * 2;
    if (idx >= 256 * Kp[m]) return;
    int n  = idx / Kp[m];
    int kp = idx - n * Kp[m];
    const float* W = ws.w[z];
    float x0 = (kp     < Km[m]) ? W[(size_t)kp*256 + n]     : 0.f;
    float x1 = (kp + 1 < Km[m]) ? W[(size_t)(kp+1)*256 + n] : 0.f;
    __half2 hh; hh.x = __float2half(x0); hh.y = __float2half(x1);
    size_t o = (size_t)t*256*APAD + (size_t)n*APAD + colA[m] + kp;
    *(__half2*)&g_wh[o] = hh;
}

__global__ void __launch_bounds__(256) conv_fcw_kernel(const float* __restrict__ fcw)
{
    int idx = (blockIdx.x * 256 + threadIdx.x) * 2;
    int n = idx >> 8, k = idx & 255;
    __half2 hh;
    hh.x = __float2half(fcw[(size_t)k*256 + n]);
    hh.y = __float2half(fcw[(size_t)(k+1)*256 + n]);
    *(__half2*)&g_fch[n*256 + k] = hh;
}

// ---------------- mma.sync split-fp16 GEMM -------------------------------------
// R9 shape: 256 threads, 8 warps (2x4), CTA tile 128x128, warp tile 64x32.
// nprod=2: pass1 Ah, pass2 Al;  nprod=1: Ah only
// ohalf=1: write __half output; 0: float output.
struct GP {
    const __half *Ah, *Al, *B;
    int ldA, ldB, colA, colB, Kp, nprod, ohalf;
    const float* bias;
    void* C; int ldc;
};

// stage: A 128x144B + B 128x144B  (K-chunk 64, 144B padded rows); 3 stages
#define SOFF_B 18432
#define SSTG   36864
#define NSTAGE 3
#define SMEM_GEMM (NSTAGE*SSTG)   // 110592 -> 2 CTAs/SM (216KB)

__device__ __forceinline__ void gemm_body(const GP p)
{
    extern __shared__ __align__(16) char dsm[];
    const int tid  = threadIdx.x;
    const int lane = tid & 31, wid = tid >> 5;
    const int wm = wid >> 2, wn = wid & 3;            // 2x4 warp grid
    const int row0 = blockIdx.y * 128, col0 = blockIdx.x * 128;
    const uint32_t sbase = su32(dsm);

    const int ck = p.Kp >> 6;          // K=64 chunks per segment
    const int nchunk = p.nprod * ck;

    auto load_chunk = [&](int c, int buf) {
        int seg = (c >= ck);
        int kc  = seg ? c - ck : c;
        const __half* A  = seg ? p.Al : p.Ah;
        const __half* As = A + (size_t)row0 * p.ldA + p.colA + kc * 64;
        const __half* Bs = p.B + (size_t)col0 * p.ldB + p.colB + kc * 64;
        uint32_t Sd = sbase + buf * SSTG;
#pragma unroll
        for (int i = 0; i < 4; i++) {
            int id = i * 256 + tid, r = id >> 3, kg = id & 7;
            cp16(Sd + r * 144 + kg * 16, As + (size_t)r * p.ldA + kg * 8);
            cp16(Sd + SOFF_B + r * 144 + kg * 16, Bs + (size_t)r * p.ldB + kg * 8);
        }
    };

    float acc[4][4][4];
#pragma unroll
    for (int i = 0; i < 4; i++)
#pragma unroll
        for (int j = 0; j < 4; j++)
#pragma unroll
            for (int r = 0; r < 4; r++) acc[i][j][r] = 0.f;

    load_chunk(0, 0); cp_commit();

    // per-lane ldmatrix byte offsets (144B smem row stride)
    const uint32_t a_off = (uint32_t)((wm * 64 + (lane & 15)) * 144 + ((lane >> 4) << 4));
    const uint32_t b_off = (uint32_t)((wn * 32 + (lane & 7) + ((lane & 16) >> 1)) * 144
                                      + ((lane & 8) << 1));

    int bufc = 0;                       // buffer holding chunk c
    for (int c = 0; c < nchunk; c++) {
        // issue chunk c+1 into buffer (c+1)%3; its previous readers were chunk
        // c-2, fenced by iteration c-1's __syncthreads -> WAR-safe.
        int bnew = bufc + 1; if (bnew == NSTAGE) bnew = 0;
        if (c + 1 < nchunk) {
            load_chunk(c + 1, bnew); cp_commit();
            asm volatile("cp.async.wait_group 1;" ::: "memory");
        } else {
            asm volatile("cp.async.wait_group 0;" ::: "memory");
        }
        __syncthreads();

        const uint32_t Sd = sbase + bufc * SSTG;
        const uint32_t Ab = Sd + a_off;
        const uint32_t Bb = Sd + SOFF_B + b_off;
#pragma unroll
        for (int kstep = 0; kstep < 4; kstep++) {
            const uint32_t kk = kstep * 32;
            uint32_t a[4][4], b[2][4];
#pragma unroll
            for (int mt = 0; mt < 4; mt++)
                ldm_x4(a[mt][0], a[mt][1], a[mt][2], a[mt][3],
                       Ab + mt * (16 * 144) + kk);
#pragma unroll
            for (int ng = 0; ng < 2; ng++)
                ldm_x4(b[ng][0], b[ng][1], b[ng][2], b[ng][3],
                       Bb + ng * (16 * 144) + kk);
#pragma unroll
            for (int mt = 0; mt < 4; mt++)
#pragma unroll
                for (int nt = 0; nt < 4; nt++)
                    mma_f16(acc[mt][nt],
                            a[mt][0], a[mt][1], a[mt][2], a[mt][3],
                            b[nt >> 1][(nt & 1) * 2], b[nt >> 1][(nt & 1) * 2 + 1]);
        }
        bufc = bnew;
    }

    // epilogue
    const int grp = lane >> 2, tig = lane & 3;
#pragma unroll
    for (int mt = 0; mt < 4; mt++) {
        int r = row0 + wm * 64 + mt * 16 + grp;
#pragma unroll
        for (int nt = 0; nt < 4; nt++) {
            int col = col0 + wn * 32 + nt * 8 + tig * 2;
            float b0 = p.bias[col], b1 = p.bias[col + 1];
            float v00 = acc[mt][nt][0] + b0, v01 = acc[mt][nt][1] + b1;
            float v10 = acc[mt][nt][2] + b0, v11 = acc[mt][nt][3] + b1;
            if (p.ohalf) {
                __half* C = (__half*)p.C;
                __half2 lo; lo.x = __float2half(v00); lo.y = __float2half(v01);
                __half2 hi; hi.x = __float2half(v10); hi.y = __float2half(v11);
                *(__half2*)(C + (size_t)r * p.ldc + col) = lo;
                *(__half2*)(C + (size_t)(r + 8) * p.ldc + col) = hi;
            } else {
                float* C = (float*)p.C;
                float2 lo; lo.x = v00; lo.y = v01;
                float2 hi; hi.x = v10; hi.y = v11;
                *(float2*)(C + (size_t)r * p.ldc + col) = lo;
                *(float2*)(C + (size_t)(r + 8) * p.ldc + col) = hi;
            }
        }
    }
}

struct B9 { const float* b[9]; };

// z = m*3 + t  (q/k/v of same modality adjacent: A stays L2-hot)
// Q,K: single product, fp16 output (logits path: L1-norm + softmax tolerant)
// V: full 2-product split, fp32 output (direct linear path to output)
__global__ void __launch_bounds__(256, 2) qkv_gemm_kernel(B9 biases)
{
    const int colA[3] = {0, 2048, 2560};
    const int Kp[3]   = {2048, 512, 448};
    int z = blockIdx.z, m = z / 3, t = z - m * 3;
    GP p;
    p.Ah = g_ah; p.Al = g_al; p.ldA = APAD; p.colA = colA[m];
    p.B  = g_wh + (size_t)t * 256 * APAD;
    p.ldB = APAD; p.colB = colA[m];
    p.Kp = Kp[m];
    p.nprod = (t == 2) ? 2 : 1;
    p.ohalf = (t == 2) ? 0 : 1;
    p.bias = biases.b[t * 3 + m];
    if (t == 0)      p.C = (void*)(g_qh + m * 256);
    else if (t == 1) p.C = (void*)(g_kh + m * 256);
    else             p.C = (void*)(g_v  + m * 256);
    p.ldc = QKV_LD;
    gemm_body(p);
}

// fc: single product (o in fp16; LN downstream tolerates ~2.4e-4)
__global__ void __launch_bounds__(256, 2) fc_gemm_kernel(const float* fc_b)
{
    GP p;
    p.Ah = g_oh; p.Al = g_oh; p.ldA = 256; p.colA = 0;
    p.B  = g_fch; p.ldB = 256; p.colB = 0;
    p.Kp = 256; p.nprod = 1; p.ohalf = 0;
    p.bias = fc_b; p.C = (void*)g_fc; p.ldc = 256;
    gemm_body(p);
}

// ------------- attention logits + global min (fp16 q,k) -----------------------
__global__ void __launch_bounds__(256) attn_logits_kernel()
{
    int t  = blockIdx.x * blockDim.x + threadIdx.x;
    int bs = t >> 3, h = t & 7;
    const uint4* qb = (const uint4*)g_qh + (size_t)bs * 96 + h * 4;
    const uint4* kb = (const uint4*)g_kh + (size_t)bs * 96 + h * 4;

    uint4 kr[3][4];
#pragma unroll
    for (int n = 0; n < 3; n++)
#pragma unroll
        for (int j = 0; j < 4; j++) kr[n][j] = kb[n * 32 + j];

    float lmin = 3.4e38f;
#pragma unroll
    for (int m = 0; m < 3; m++) {
        uint4 qv[4];
#pragma unroll
        for (int j = 0; j < 4; j++) qv[j] = qb[m * 32 + j];
#pragma unroll
        for (int n = 0; n < 3; n++) {
            float s = 0.f;
#pragma unroll
            for (int j = 0; j < 4; j++) s += dot8(qv[j], kr[n][j]);
            s *= TEMP_INV;
            g_logits[t * 9 + m * 3 + n] = s;
            lmin = fminf(lmin, s);
        }
    }
#pragma unroll
    for (int off = 16; off; off >>= 1)
        lmin = fminf(lmin, __shfl_xor_sync(0xFFFFFFFFu, lmin, off));
    if ((threadIdx.x & 31) == 0) atomicMin(&g_minkey, f2key(lmin));
}

// ------------- scale / L1 / softmax / PV -> fp16 o ----------------------------
__global__ void __launch_bounds__(256) attn_softmax_o_kernel()
{
    int t  = blockIdx.x * blockDim.x + threadIdx.x;
    int bs = t >> 3, h = t & 7;
    float inv = 1.0f / fabsf(key2f(g_minkey));

    const float* lg = g_logits + t * 9;
    const float4* vb = (const float4*)(g_v + bs * QKV_LD + h * 32);
    size_t obase = (size_t)bs * QKV_LD + h * 32;

#pragma unroll
    for (int m = 0; m < 3; m++) {
        float r0 = lg[m*3+0]*inv, r1 = lg[m*3+1]*inv, r2 = lg[m*3+2]*inv;
        float l1 = fmaxf(fabsf(r0) + fabsf(r1) + fabsf(r2), 1e-12f);
        r0 /= l1; r1 /= l1; r2 /= l1;
        float mx = fmaxf(r0, fmaxf(r1, r2));
        float e0 = expf(r0-mx), e1 = expf(r1-mx), e2 = expf(r2-mx);
        float es = e0 + e1 + e2;
        float p0 = e0/es, p1 = e1/es, p2 = e2/es;

        __half2* oh2 = (__half2*)&g_oh[obase + m * 256];
#pragma unroll
        for (int j = 0; j < 8; j++) {
            float4 v0 = vb[j], v1 = vb[64+j], v2 = vb[128+j];
            __half2 h01, h23;
            h01.x = __float2half(p0*v0.x + p1*v1.x + p2*v2.x);
            h01.y = __float2half(p0*v0.y + p1*v1.y + p2*v2.y);
            h23.x = __float2half(p0*v0.z + p1*v1.z + p2*v2.z);
            h23.y = __float2half(p0*v0.w + p1*v1.w + p2*v2.w);
            oh2[j*2]   = h01;
            oh2[j*2+1] = h23;
        }
    }
}

// ------------- fused residual + layernorm + out GEMM --------------------------
__global__ void __launch_bounds__(256) ln_out_kernel(
    const float* __restrict__ ln_g, const float* __restrict__ ln_b,
    const float* __restrict__ out_w, const float* __restrict__ out_b,
    float* __restrict__ out)
{
    __shared__ float red[8][8];
    __shared__ float bcast[8];

    int s = blockIdx.x, tid = threadIdx.x;
    int lane = tid & 31, wid = tid >> 5;

    float x[3];
#pragma unroll
    for (int m = 0; m < 3; m++) {
        size_t r = (size_t)(s * 3 + m) * 256 + tid;
        x[m] = g_fc[r] + g_v[r];
    }

    float v6[6] = {x[0], x[1], x[2], x[0]*x[0], x[1]*x[1], x[2]*x[2]};
#pragma unroll
    for (int off = 16; off; off >>= 1)
#pragma unroll
        for (int i = 0; i < 6; i++)
            v6[i] += __shfl_xor_sync(0xFFFFFFFFu, v6[i], off);
    if (lane < 6) red[wid][lane] = v6[lane];
    __syncthreads();
    if (wid == 0) {
#pragma unroll
        for (int i = 0; i < 6; i++) {
            float t = (lane < 8) ? red[lane][i] : 0.f;
#pragma unroll
            for (int off = 4; off; off >>= 1)
                t += __shfl_xor_sync(0xFFFFFFFFu, t, off);
            if (lane == 0) bcast[i] = t;
        }
    }
    __syncthreads();

    float gg = ln_g[tid], bb = ln_b[tid];
    float acc[5] = {0.f, 0.f, 0.f, 0.f, 0.f};
#pragma unroll
    for (int m = 0; m < 3; m++) {
        float mu  = bcast[m] * (1.0f / 256.0f);
        float var = bcast[m + 3] * (1.0f / 256.0f) - mu * mu;
        float rstd = rsqrtf(var + LN_EPS);
        float xn = (x[m] - mu) * rstd * gg + bb;
        const float* wrow = out_w + (size_t)(m * 256 + tid) * 5;
#pragma unroll
        for (int c = 0; c < 5; c++) acc[c] = fmaf(xn, wrow[c], acc[c]);
    }
#pragma unroll
    for (int off = 16; off; off >>= 1)
#pragma unroll
        for (int c = 0; c < 5; c++)
            acc[c] += __shfl_xor_sync(0xFFFFFFFFu, acc[c], off);
    if (lane < 5) red[wid][lane] = acc[lane];
    __syncthreads();
    if (wid == 0 && lane < 5) {
        float t = 0.f;
#pragma unroll
        for (int w = 0; w < 8; w++) t += red[w][lane];
        out[s * 5 + lane] = t + out_b[lane];
    }
}

// ==============================================================================
extern "C" void kernel_launch(void* const* d_in, const int* in_sizes, int n_in,
                              void* d_out, int out_size)
{
    const float* X = (const float*)d_in[0];
    W9 ws; B9 bs;
    for (int t = 0; t < 3; t++)
        for (int m = 0; m < 3; m++) {
            ws.w[t*3+m] = (const float*)d_in[1 + t*6 + m*2];
            bs.b[t*3+m] = (const float*)d_in[2 + t*6 + m*2];
        }
    const float* fc_w  = (const float*)d_in[19];
    const float* fc_b  = (const float*)d_in[20];
    const float* ln_g  = (const float*)d_in[21];
    const float* ln_b  = (const float*)d_in[22];
    const float* out_w = (const float*)d_in[23];
    const float* out_b = (const float*)d_in[24];
    float* out = (float*)d_out;

    static int smem_set = 0;
    if (!smem_set) {
        cudaFuncSetAttribute(qkv_gemm_kernel, cudaFuncAttributeMaxDynamicSharedMemorySize, SMEM_GEMM);
        cudaFuncSetAttribute(fc_gemm_kernel,  cudaFuncAttributeMaxDynamicSharedMemorySize, SMEM_GEMM);
        smem_set = 1;
    }

    init_min_kernel<<<1, 1>>>();                    // idx 0
    conv_x_kernel<<<dim3(6, BSZ), 256>>>(X);        // idx 1
    conv_w_kernel<<<dim3(1024, 1, 9), 256>>>(ws);   // idx 2

    qkv_gemm_kernel<<<dim3(2, BSZ/128, 9), 256, SMEM_GEMM>>>(bs);  // idx 3 -> ncu target

    conv_fcw_kernel<<<128, 256>>>(fc_w);            // idx 4

    attn_logits_kernel<<<(BSZ*8)/256, 256>>>();
    attn_softmax_o_kernel<<<(BSZ*8)/256, 256>>>();

    fc_gemm_kernel<<<dim3(2, NROWS/128, 1), 256, SMEM_GEMM>>>(fc_b);

    ln_out_kernel<<<BSZ, 256>>>(ln_g, ln_b, out_w, out_b, out);
}

// round 13
// speedup vs baseline: 1.4368x; 1.2802x over previous
#include <cuda_runtime.h>
#include <cuda_fp16.h>
#include <cstdint>

#define BSZ    16384
#define QKV_LD 768
#define NROWS  (BSZ*3)
#define LN_EPS 1e-6f
#define TEMP_INV 0.17677669529663687f
#define APAD   3072      // A layout stride; used cols = 2048+512+448 = 3008

// ---------------- scratch (static device arrays; no cudaMalloc) --------------
__device__ __align__(16) float g_logits[BSZ*8*9];
__device__ unsigned g_minkey;

__device__ __align__(16) __half g_qh [BSZ*QKV_LD];
__device__ __align__(16) __half g_kh [BSZ*QKV_LD];
__device__ __align__(16) __half g_vh [BSZ*QKV_LD];
__device__ __align__(16) __half g_fco[BSZ*QKV_LD];
__device__ __align__(16) __half g_ah[(size_t)BSZ*APAD];
__device__ __align__(16) __half g_wh[(size_t)3*256*APAD];
__device__ __align__(16) __half g_oh[(size_t)NROWS*256];
__device__ __align__(16) __half g_fch[256*256];

// ---------------- small helpers ----------------------------------------------
__device__ __forceinline__ unsigned f2key(float f) {
    unsigned u = __float_as_uint(f);
    return (u & 0x80000000u) ? ~u : (u | 0x80000000u);
}
__device__ __forceinline__ float key2f(unsigned k) {
    unsigned u = (k & 0x80000000u) ? (k & 0x7FFFFFFFu) : ~k;
    return __uint_as_float(u);
}
__global__ void init_min_kernel() { g_minkey = 0xFFFFFFFFu; }

__device__ __forceinline__ uint32_t su32(const void* p) {
    return (uint32_t)__cvta_generic_to_shared(p);
}
__device__ __forceinline__ void cp16(uint32_t dst, const void* src) {
    asm volatile("cp.async.cg.shared.global [%0], [%1], 16;"
                 :: "r"(dst), "l"(src) : "memory");
}
__device__ __forceinline__ void cp_commit() {
    asm volatile("cp.async.commit_group;" ::: "memory");
}
__device__ __forceinline__ void ldm_x4(uint32_t& r0, uint32_t& r1, uint32_t& r2,
                                       uint32_t& r3, uint32_t addr) {
    asm volatile("ldmatrix.sync.aligned.m8n8.x4.shared.b16 {%0,%1,%2,%3}, [%4];"
                 : "=r"(r0), "=r"(r1), "=r"(r2), "=r"(r3) : "r"(addr));
}
__device__ __forceinline__ void mma_f16(float* c, uint32_t a0, uint32_t a1,
                                        uint32_t a2, uint32_t a3,
                                        uint32_t b0, uint32_t b1) {
    asm volatile(
        "mma.sync.aligned.m16n8k16.row.col.f32.f16.f16.f32 "
        "{%0,%1,%2,%3}, {%4,%5,%6,%7}, {%8,%9}, {%0,%1,%2,%3};"
        : "+f"(c[0]), "+f"(c[1]), "+f"(c[2]), "+f"(c[3])
        : "r"(a0), "r"(a1), "r"(a2), "r"(a3), "r"(b0), "r"(b1));
}
__device__ __forceinline__ float dot8(uint4 a, uint4 b) {
    const __half2* pa = (const __half2*)&a;
    const __half2* pb = (const __half2*)&b;
    float s = 0.f;
#pragma unroll
    for (int i = 0; i < 4; i++) {
        float2 fa = __half22float2(pa[i]), fb = __half22float2(pb[i]);
        s = fmaf(fa.x, fb.x, s);
        s = fmaf(fa.y, fb.y, s);
    }
    return s;
}

// ---------------- conversion kernels -----------------------------------------
// padded segments: [0,2048) <- X[0,2000); [2048,2560) <- X[2000,2500); [2560,3008) <- X[2500,2900)
// 4 cols per thread, float4 reads (all 4-col blocks are fully in-range or fully pad)
__global__ void __launch_bounds__(256) conv_x_kernel(const float* __restrict__ X)
{
    int col = (blockIdx.x * 256 + threadIdx.x) * 4;
    if (col >= 3008) return;
    int row = blockIdx.y;

    float4 v = make_float4(0.f, 0.f, 0.f, 0.f);
    if (col < 2048)      { if (col < 2000) v = *(const float4*)(X + (size_t)row*2900 + col); }
    else if (col < 2560) { int c = col-2048; if (c < 500) v = *(const float4*)(X + (size_t)row*2900 + 2000 + c); }
    else                 { int c = col-2560; if (c < 400) v = *(const float4*)(X + (size_t)row*2900 + 2500 + c); }

    __half2 h0; h0.x = __float2half(v.x); h0.y = __float2half(v.y);
    __half2 h1; h1.x = __float2half(v.z); h1.y = __float2half(v.w);
    uint2 pk; pk.x = *(uint32_t*)&h0; pk.y = *(uint32_t*)&h1;
    *(uint2*)&g_ah[(size_t)row*APAD + col] = pk;
}

struct W9 { const float* w[9]; };
__global__ void __launch_bounds__(256) conv_w_kernel(W9 ws)
{
    const int Km[3]   = {2000, 500, 400};
    const int Kp[3]   = {2048, 512, 448};
    const int colA[3] = {0, 2048, 2560};
    int z = blockIdx.z, t = z / 3, m = z - t * 3;
    int idx = (blockIdx.x * 256 + threadIdx.x) * 2;
    if (idx >= 256 * Kp[m]) return;
    int n  = idx / Kp[m];
    int kp = idx - n * Kp[m];
    const float* W = ws.w[z];
    float x0 = (kp     < Km[m]) ? W[(size_t)kp*256 + n]     : 0.f;
    float x1 = (kp + 1 < Km[m]) ? W[(size_t)(kp+1)*256 + n] : 0.f;
    __half2 hh; hh.x = __float2half(x0); hh.y = __float2half(x1);
    size_t o = (size_t)t*256*APAD + (size_t)n*APAD + colA[m] + kp;
    *(__half2*)&g_wh[o] = hh;
}

__global__ void __launch_bounds__(256) conv_fcw_kernel(const float* __restrict__ fcw)
{
    int idx = (blockIdx.x * 256 + threadIdx.x) * 2;
    int n = idx >> 8, k = idx & 255;
    __half2 hh;
    hh.x = __float2half(fcw[(size_t)k*256 + n]);
    hh.y = __float2half(fcw[(size_t)(k+1)*256 + n]);
    *(__half2*)&g_fch[n*256 + k] = hh;
}

// ---------------- mma.sync fp16 GEMM -------------------------------------------
// R9 shape: 256 threads, 8 warps (2x4), CTA tile 128x128, warp tile 64x32.
// Single product (A-hi only); fp16 or fp32 output.
struct GP {
    const __half *Ah, *B;
    int ldA, ldB, colA, colB, Kp, ohalf;
    const float* bias;
    void* C; int ldc;
};

// stage: A 128x144B + B 128x144B  (K-chunk 64, 144B padded rows); 3 stages
#define SOFF_B 18432
#define SSTG   36864
#define NSTAGE 3
#define SMEM_GEMM (NSTAGE*SSTG)   // 110592 -> 2 CTAs/SM (216KB)

__device__ __forceinline__ void gemm_body(const GP p)
{
    extern __shared__ __align__(16) char dsm[];
    const int tid  = threadIdx.x;
    const int lane = tid & 31, wid = tid >> 5;
    const int wm = wid >> 2, wn = wid & 3;            // 2x4 warp grid
    const int row0 = blockIdx.y * 128, col0 = blockIdx.x * 128;
    const uint32_t sbase = su32(dsm);

    const int nchunk = p.Kp >> 6;      // K=64 chunks

    auto load_chunk = [&](int c, int buf) {
        const __half* As = p.Ah + (size_t)row0 * p.ldA + p.colA + c * 64;
        const __half* Bs = p.B  + (size_t)col0 * p.ldB + p.colB + c * 64;
        uint32_t Sd = sbase + buf * SSTG;
#pragma unroll
        for (int i = 0; i < 4; i++) {
            int id = i * 256 + tid, r = id >> 3, kg = id & 7;
            cp16(Sd + r * 144 + kg * 16, As + (size_t)r * p.ldA + kg * 8);
            cp16(Sd + SOFF_B + r * 144 + kg * 16, Bs + (size_t)r * p.ldB + kg * 8);
        }
    };

    float acc[4][4][4];
#pragma unroll
    for (int i = 0; i < 4; i++)
#pragma unroll
        for (int j = 0; j < 4; j++)
#pragma unroll
            for (int r = 0; r < 4; r++) acc[i][j][r] = 0.f;

    load_chunk(0, 0); cp_commit();

    // per-lane ldmatrix byte offsets (144B smem row stride)
    const uint32_t a_off = (uint32_t)((wm * 64 + (lane & 15)) * 144 + ((lane >> 4) << 4));
    const uint32_t b_off = (uint32_t)((wn * 32 + (lane & 7) + ((lane & 16) >> 1)) * 144
                                      + ((lane & 8) << 1));

    int bufc = 0;                       // buffer holding chunk c
    for (int c = 0; c < nchunk; c++) {
        int bnew = bufc + 1; if (bnew == NSTAGE) bnew = 0;
        if (c + 1 < nchunk) {
            load_chunk(c + 1, bnew); cp_commit();
            asm volatile("cp.async.wait_group 1;" ::: "memory");
        } else {
            asm volatile("cp.async.wait_group 0;" ::: "memory");
        }
        __syncthreads();

        const uint32_t Sd = sbase + bufc * SSTG;
        const uint32_t Ab = Sd + a_off;
        const uint32_t Bb = Sd + SOFF_B + b_off;
#pragma unroll
        for (int kstep = 0; kstep < 4; kstep++) {
            const uint32_t kk = kstep * 32;
            uint32_t a[4][4], b[2][4];
#pragma unroll
            for (int mt = 0; mt < 4; mt++)
                ldm_x4(a[mt][0], a[mt][1], a[mt][2], a[mt][3],
                       Ab + mt * (16 * 144) + kk);
#pragma unroll
            for (int ng = 0; ng < 2; ng++)
                ldm_x4(b[ng][0], b[ng][1], b[ng][2], b[ng][3],
                       Bb + ng * (16 * 144) + kk);
#pragma unroll
            for (int mt = 0; mt < 4; mt++)
#pragma unroll
                for (int nt = 0; nt < 4; nt++)
                    mma_f16(acc[mt][nt],
                            a[mt][0], a[mt][1], a[mt][2], a[mt][3],
                            b[nt >> 1][(nt & 1) * 2], b[nt >> 1][(nt & 1) * 2 + 1]);
        }
        bufc = bnew;
    }

    // epilogue
    const int grp = lane >> 2, tig = lane & 3;
#pragma unroll
    for (int mt = 0; mt < 4; mt++) {
        int r = row0 + wm * 64 + mt * 16 + grp;
#pragma unroll
        for (int nt = 0; nt < 4; nt++) {
            int col = col0 + wn * 32 + nt * 8 + tig * 2;
            float b0 = p.bias[col], b1 = p.bias[col + 1];
            float v00 = acc[mt][nt][0] + b0, v01 = acc[mt][nt][1] + b1;
            float v10 = acc[mt][nt][2] + b0, v11 = acc[mt][nt][3] + b1;
            if (p.ohalf) {
                __half* C = (__half*)p.C;
                __half2 lo; lo.x = __float2half(v00); lo.y = __float2half(v01);
                __half2 hi; hi.x = __float2half(v10); hi.y = __float2half(v11);
                *(__half2*)(C + (size_t)r * p.ldc + col) = lo;
                *(__half2*)(C + (size_t)(r + 8) * p.ldc + col) = hi;
            } else {
                float* C = (float*)p.C;
                float2 lo; lo.x = v00; lo.y = v01;
                float2 hi; hi.x = v10; hi.y = v11;
                *(float2*)(C + (size_t)r * p.ldc + col) = lo;
                *(float2*)(C + (size_t)(r + 8) * p.ldc + col) = hi;
            }
        }
    }
}

struct B9 { const float* b[9]; };

// z = m*3 + t  (q/k/v of same modality adjacent: A stays L2-hot)
// All single-product, fp16 outputs (downstream paths all round to fp16 anyway)
__global__ void __launch_bounds__(256, 2) qkv_gemm_kernel(B9 biases)
{
    const int colA[3] = {0, 2048, 2560};
    const int Kp[3]   = {2048, 512, 448};
    int z = blockIdx.z, m = z / 3, t = z - m * 3;
    GP p;
    p.Ah = g_ah; p.ldA = APAD; p.colA = colA[m];
    p.B  = g_wh + (size_t)t * 256 * APAD;
    p.ldB = APAD; p.colB = colA[m];
    p.Kp = Kp[m];
    p.ohalf = 1;
    p.bias = biases.b[t * 3 + m];
    if (t == 0)      p.C = (void*)(g_qh + m * 256);
    else if (t == 1) p.C = (void*)(g_kh + m * 256);
    else             p.C = (void*)(g_vh + m * 256);
    p.ldc = QKV_LD;
    gemm_body(p);
}

__global__ void __launch_bounds__(256, 2) fc_gemm_kernel(const float* fc_b)
{
    GP p;
    p.Ah = g_oh; p.ldA = 256; p.colA = 0;
    p.B  = g_fch; p.ldB = 256; p.colB = 0;
    p.Kp = 256; p.ohalf = 1;
    p.bias = fc_b; p.C = (void*)g_fco; p.ldc = 256;
    gemm_body(p);
}

// ------------- attention logits + global min (fp16 q,k) -----------------------
__global__ void __launch_bounds__(256) attn_logits_kernel()
{
    int t  = blockIdx.x * blockDim.x + threadIdx.x;
    int bs = t >> 3, h = t & 7;
    const uint4* qb = (const uint4*)g_qh + (size_t)bs * 96 + h * 4;
    const uint4* kb = (const uint4*)g_kh + (size_t)bs * 96 + h * 4;

    uint4 kr[3][4];
#pragma unroll
    for (int n = 0; n < 3; n++)
#pragma unroll
        for (int j = 0; j < 4; j++) kr[n][j] = kb[n * 32 + j];

    float lmin = 3.4e38f;
#pragma unroll
    for (int m = 0; m < 3; m++) {
        uint4 qv[4];
#pragma unroll
        for (int j = 0; j < 4; j++) qv[j] = qb[m * 32 + j];
#pragma unroll
        for (int n = 0; n < 3; n++) {
            float s = 0.f;
#pragma unroll
            for (int j = 0; j < 4; j++) s += dot8(qv[j], kr[n][j]);
            s *= TEMP_INV;
            g_logits[t * 9 + m * 3 + n] = s;
            lmin = fminf(lmin, s);
        }
    }
#pragma unroll
    for (int off = 16; off; off >>= 1)
        lmin = fminf(lmin, __shfl_xor_sync(0xFFFFFFFFu, lmin, off));
    if ((threadIdx.x & 31) == 0) atomicMin(&g_minkey, f2key(lmin));
}

// ------------- scale / L1 / softmax / PV (fp16 v in, fp16 o out) --------------
__global__ void __launch_bounds__(256) attn_softmax_o_kernel()
{
    int t  = blockIdx.x * blockDim.x + threadIdx.x;
    int bs = t >> 3, h = t & 7;
    float inv = 1.0f / fabsf(key2f(g_minkey));

    const float* lg = g_logits + t * 9;
    const uint4* vb = (const uint4*)g_vh + (size_t)bs * 96 + h * 4;
    uint4* ob = (uint4*)g_oh + (size_t)bs * 96 + h * 4;

    uint4 vr[3][4];
#pragma unroll
    for (int n = 0; n < 3; n++)
#pragma unroll
        for (int j = 0; j < 4; j++) vr[n][j] = vb[n * 32 + j];

#pragma unroll
    for (int m = 0; m < 3; m++) {
        float r0 = lg[m*3+0]*inv, r1 = lg[m*3+1]*inv, r2 = lg[m*3+2]*inv;
        float l1 = fmaxf(fabsf(r0) + fabsf(r1) + fabsf(r2), 1e-12f);
        r0 /= l1; r1 /= l1; r2 /= l1;
        float mx = fmaxf(r0, fmaxf(r1, r2));
        float e0 = expf(r0-mx), e1 = expf(r1-mx), e2 = expf(r2-mx);
        float es = e0 + e1 + e2;
        float p0 = e0/es, p1 = e1/es, p2 = e2/es;

#pragma unroll
        for (int j = 0; j < 4; j++) {
            const __half2* a0 = (const __half2*)&vr[0][j];
            const __half2* a1 = (const __half2*)&vr[1][j];
            const __half2* a2 = (const __half2*)&vr[2][j];
            uint4 o;
            __half2* oh = (__half2*)&o;
#pragma unroll
            for (int i = 0; i < 4; i++) {
                float2 f0 = __half22float2(a0[i]);
                float2 f1 = __half22float2(a1[i]);
                float2 f2 = __half22float2(a2[i]);
                __half2 r;
                r.x = __float2half(p0*f0.x + p1*f1.x + p2*f2.x);
                r.y = __float2half(p0*f0.y + p1*f1.y + p2*f2.y);
                oh[i] = r;
            }
            ob[m * 32 + j] = o;
        }
    }
}

// ------------- fused residual + layernorm + out GEMM --------------------------
__global__ void __launch_bounds__(256) ln_out_kernel(
    const float* __restrict__ ln_g, const float* __restrict__ ln_b,
    const float* __restrict__ out_w, const float* __restrict__ out_b,
    float* __restrict__ out)
{
    __shared__ float red[8][8];
    __shared__ float bcast[8];

    int s = blockIdx.x, tid = threadIdx.x;
    int lane = tid & 31, wid = tid >> 5;

    float x[3];
#pragma unroll
    for (int m = 0; m < 3; m++) {
        size_t r = (size_t)(s * 3 + m) * 256 + tid;
        x[m] = __half2float(g_fco[r]) + __half2float(g_vh[r]);
    }

    float v6[6] = {x[0], x[1], x[2], x[0]*x[0], x[1]*x[1], x[2]*x[2]};
#pragma unroll
    for (int off = 16; off; off >>= 1)
#pragma unroll
        for (int i = 0; i < 6; i++)
            v6[i] += __shfl_xor_sync(0xFFFFFFFFu, v6[i], off);
    if (lane < 6) red[wid][lane] = v6[lane];
    __syncthreads();
    if (wid == 0) {
#pragma unroll
        for (int i = 0; i < 6; i++) {
            float t = (lane < 8) ? red[lane][i] : 0.f;
#pragma unroll
            for (int off = 4; off; off >>= 1)
                t += __shfl_xor_sync(0xFFFFFFFFu, t, off);
            if (lane == 0) bcast[i] = t;
        }
    }
    __syncthreads();

    float gg = ln_g[tid], bb = ln_b[tid];
    float acc[5] = {0.f, 0.f, 0.f, 0.f, 0.f};
#pragma unroll
    for (int m = 0; m < 3; m++) {
        float mu  = bcast[m] * (1.0f / 256.0f);
        float var = bcast[m + 3] * (1.0f / 256.0f) - mu * mu;
        float rstd = rsqrtf(var + LN_EPS);
        float xn = (x[m] - mu) * rstd * gg + bb;
        const float* wrow = out_w + (size_t)(m * 256 + tid) * 5;
#pragma unroll
        for (int c = 0; c < 5; c++) acc[c] = fmaf(xn, wrow[c], acc[c]);
    }
#pragma unroll
    for (int off = 16; off; off >>= 1)
#pragma unroll
        for (int c = 0; c < 5; c++)
            acc[c] += __shfl_xor_sync(0xFFFFFFFFu, acc[c], off);
    if (lane < 5) red[wid][lane] = acc[lane];
    __syncthreads();
    if (wid == 0 && lane < 5) {
        float t = 0.f;
#pragma unroll
        for (int w = 0; w < 8; w++) t += red[w][lane];
        out[s * 5 + lane] = t + out_b[lane];
    }
}

// ==============================================================================
extern "C" void kernel_launch(void* const* d_in, const int* in_sizes, int n_in,
                              void* d_out, int out_size)
{
    const float* X = (const float*)d_in[0];
    W9 ws; B9 bs;
    for (int t = 0; t < 3; t++)
        for (int m = 0; m < 3; m++) {
            ws.w[t*3+m] = (const float*)d_in[1 + t*6 + m*2];
            bs.b[t*3+m] = (const float*)d_in[2 + t*6 + m*2];
        }
    const float* fc_w  = (const float*)d_in[19];
    const float* fc_b  = (const float*)d_in[20];
    const float* ln_g  = (const float*)d_in[21];
    const float* ln_b  = (const float*)d_in[22];
    const float* out_w = (const float*)d_in[23];
    const float* out_b = (const float*)d_in[24];
    float* out = (float*)d_out;

    static int smem_set = 0;
    if (!smem_set) {
        cudaFuncSetAttribute(qkv_gemm_kernel, cudaFuncAttributeMaxDynamicSharedMemorySize, SMEM_GEMM);
        cudaFuncSetAttribute(fc_gemm_kernel,  cudaFuncAttributeMaxDynamicSharedMemorySize, SMEM_GEMM);
        smem_set = 1;
    }

    init_min_kernel<<<1, 1>>>();                    // idx 0
    conv_x_kernel<<<dim3(3, BSZ), 256>>>(X);        // idx 1
    conv_w_kernel<<<dim3(1024, 1, 9), 256>>>(ws);   // idx 2

    qkv_gemm_kernel<<<dim3(2, BSZ/128, 9), 256, SMEM_GEMM>>>(bs);  // idx 3 -> ncu target

    conv_fcw_kernel<<<128, 256>>>(fc_w);            // idx 4

    attn_logits_kernel<<<(BSZ*8)/256, 256>>>();
    attn_softmax_o_kernel<<<(BSZ*8)/256, 256>>>();

    fc_gemm_kernel<<<dim3(2, NROWS/128, 1), 256, SMEM_GEMM>>>(fc_b);

    ln_out_kernel<<<BSZ, 256>>>(ln_g, ln_b, out_w, out_b, out);
}

// round 14
// speedup vs baseline: 1.4614x; 1.0171x over previous
#include <cuda_runtime.h>
#include <cuda_fp16.h>
#include <cstdint>

#define BSZ    16384
#define QKV_LD 768
#define NROWS  (BSZ*3)
#define LN_EPS 1e-6f
#define TEMP_INV 0.17677669529663687f
#define APAD   3072      // A layout stride; used cols = 2048+512+448 = 3008

// ---------------- scratch (static device arrays; no cudaMalloc) --------------
__device__ __align__(16) __half g_qh [BSZ*QKV_LD];
__device__ __align__(16) __half g_kh [BSZ*QKV_LD];
__device__ __align__(16) __half g_vh [BSZ*QKV_LD];
__device__ __align__(16) __half g_fco[BSZ*QKV_LD];
__device__ __align__(16) __half g_ah[(size_t)BSZ*APAD];
__device__ __align__(16) __half g_wh[(size_t)3*256*APAD];
__device__ __align__(16) __half g_oh[(size_t)NROWS*256];
__device__ __align__(16) __half g_fch[256*256];

// ---------------- small helpers ----------------------------------------------
__device__ __forceinline__ uint32_t su32(const void* p) {
    return (uint32_t)__cvta_generic_to_shared(p);
}
__device__ __forceinline__ void cp16(uint32_t dst, const void* src) {
    asm volatile("cp.async.cg.shared.global [%0], [%1], 16;"
                 :: "r"(dst), "l"(src) : "memory");
}
__device__ __forceinline__ void cp_commit() {
    asm volatile("cp.async.commit_group;" ::: "memory");
}
__device__ __forceinline__ void ldm_x4(uint32_t& r0, uint32_t& r1, uint32_t& r2,
                                       uint32_t& r3, uint32_t addr) {
    asm volatile("ldmatrix.sync.aligned.m8n8.x4.shared.b16 {%0,%1,%2,%3}, [%4];"
                 : "=r"(r0), "=r"(r1), "=r"(r2), "=r"(r3) : "r"(addr));
}
__device__ __forceinline__ void mma_f16(float* c, uint32_t a0, uint32_t a1,
                                        uint32_t a2, uint32_t a3,
                                        uint32_t b0, uint32_t b1) {
    asm volatile(
        "mma.sync.aligned.m16n8k16.row.col.f32.f16.f16.f32 "
        "{%0,%1,%2,%3}, {%4,%5,%6,%7}, {%8,%9}, {%0,%1,%2,%3};"
        : "+f"(c[0]), "+f"(c[1]), "+f"(c[2]), "+f"(c[3])
        : "r"(a0), "r"(a1), "r"(a2), "r"(a3), "r"(b0), "r"(b1));
}
__device__ __forceinline__ float dot8(uint4 a, uint4 b) {
    const __half2* pa = (const __half2*)&a;
    const __half2* pb = (const __half2*)&b;
    float s = 0.f;
#pragma unroll
    for (int i = 0; i < 4; i++) {
        float2 fa = __half22float2(pa[i]), fb = __half22float2(pb[i]);
        s = fmaf(fa.x, fb.x, s);
        s = fmaf(fa.y, fb.y, s);
    }
    return s;
}

// ---------------- conversion kernels -----------------------------------------
// padded segments: [0,2048) <- X[0,2000); [2048,2560) <- X[2000,2500); [2560,3008) <- X[2500,2900)
__global__ void __launch_bounds__(256) conv_x_kernel(const float* __restrict__ X)
{
    int col = (blockIdx.x * 256 + threadIdx.x) * 4;
    if (col >= 3008) return;
    int row = blockIdx.y;

    float4 v = make_float4(0.f, 0.f, 0.f, 0.f);
    if (col < 2048)      { if (col < 2000) v = *(const float4*)(X + (size_t)row*2900 + col); }
    else if (col < 2560) { int c = col-2048; if (c < 500) v = *(const float4*)(X + (size_t)row*2900 + 2000 + c); }
    else                 { int c = col-2560; if (c < 400) v = *(const float4*)(X + (size_t)row*2900 + 2500 + c); }

    __half2 h0; h0.x = __float2half(v.x); h0.y = __float2half(v.y);
    __half2 h1; h1.x = __float2half(v.z); h1.y = __float2half(v.w);
    uint2 pk; pk.x = *(uint32_t*)&h0; pk.y = *(uint32_t*)&h1;
    *(uint2*)&g_ah[(size_t)row*APAD + col] = pk;
}

struct W9 { const float* w[9]; };
__global__ void __launch_bounds__(256) conv_w_kernel(W9 ws)
{
    const int Km[3]   = {2000, 500, 400};
    const int Kp[3]   = {2048, 512, 448};
    const int colA[3] = {0, 2048, 2560};
    int z = blockIdx.z, t = z / 3, m = z - t * 3;
    int idx = (blockIdx.x * 256 + threadIdx.x) * 2;
    if (idx >= 256 * Kp[m]) return;
    int n  = idx / Kp[m];
    int kp = idx - n * Kp[m];
    const float* W = ws.w[z];
    float x0 = (kp     < Km[m]) ? W[(size_t)kp*256 + n]     : 0.f;
    float x1 = (kp + 1 < Km[m]) ? W[(size_t)(kp+1)*256 + n] : 0.f;
    __half2 hh; hh.x = __float2half(x0); hh.y = __float2half(x1);
    size_t o = (size_t)t*256*APAD + (size_t)n*APAD + colA[m] + kp;
    *(__half2*)&g_wh[o] = hh;
}

__global__ void __launch_bounds__(256) conv_fcw_kernel(const float* __restrict__ fcw)
{
    int idx = (blockIdx.x * 256 + threadIdx.x) * 2;
    int n = idx >> 8, k = idx & 255;
    __half2 hh;
    hh.x = __float2half(fcw[(size_t)k*256 + n]);
    hh.y = __float2half(fcw[(size_t)(k+1)*256 + n]);
    *(__half2*)&g_fch[n*256 + k] = hh;
}

// ---------------- mma.sync fp16 GEMM -------------------------------------------
// 256 threads, 8 warps (2x4), CTA tile 128x128, warp tile 64x32. Single product.
struct GP {
    const __half *Ah, *B;
    int ldA, ldB, colA, colB, Kp;
    const float* bias;
    __half* C; int ldc;
};

// stage: A 128x144B + B 128x144B  (K-chunk 64, 144B padded rows); 3 stages
#define SOFF_B 18432
#define SSTG   36864
#define NSTAGE 3
#define SMEM_GEMM (NSTAGE*SSTG)   // 110592 -> 2 CTAs/SM (216KB)

__device__ __forceinline__ void gemm_body(const GP p)
{
    extern __shared__ __align__(16) char dsm[];
    const int tid  = threadIdx.x;
    const int lane = tid & 31, wid = tid >> 5;
    const int wm = wid >> 2, wn = wid & 3;            // 2x4 warp grid
    const int row0 = blockIdx.y * 128, col0 = blockIdx.x * 128;
    const uint32_t sbase = su32(dsm);

    const int nchunk = p.Kp >> 6;      // K=64 chunks

    auto load_chunk = [&](int c, int buf) {
        const __half* As = p.Ah + (size_t)row0 * p.ldA + p.colA + c * 64;
        const __half* Bs = p.B  + (size_t)col0 * p.ldB + p.colB + c * 64;
        uint32_t Sd = sbase + buf * SSTG;
#pragma unroll
        for (int i = 0; i < 4; i++) {
            int id = i * 256 + tid, r = id >> 3, kg = id & 7;
            cp16(Sd + r * 144 + kg * 16, As + (size_t)r * p.ldA + kg * 8);
            cp16(Sd + SOFF_B + r * 144 + kg * 16, Bs + (size_t)r * p.ldB + kg * 8);
        }
    };

    float acc[4][4][4];
#pragma unroll
    for (int i = 0; i < 4; i++)
#pragma unroll
        for (int j = 0; j < 4; j++)
#pragma unroll
            for (int r = 0; r < 4; r++) acc[i][j][r] = 0.f;

    load_chunk(0, 0); cp_commit();

    const uint32_t a_off = (uint32_t)((wm * 64 + (lane & 15)) * 144 + ((lane >> 4) << 4));
    const uint32_t b_off = (uint32_t)((wn * 32 + (lane & 7) + ((lane & 16) >> 1)) * 144
                                      + ((lane & 8) << 1));

    int bufc = 0;
    for (int c = 0; c < nchunk; c++) {
        int bnew = bufc + 1; if (bnew == NSTAGE) bnew = 0;
        if (c + 1 < nchunk) {
            load_chunk(c + 1, bnew); cp_commit();
            asm volatile("cp.async.wait_group 1;" ::: "memory");
        } else {
            asm volatile("cp.async.wait_group 0;" ::: "memory");
        }
        __syncthreads();

        const uint32_t Sd = sbase + bufc * SSTG;
        const uint32_t Ab = Sd + a_off;
        const uint32_t Bb = Sd + SOFF_B + b_off;
#pragma unroll
        for (int kstep = 0; kstep < 4; kstep++) {
            const uint32_t kk = kstep * 32;
            uint32_t a[4][4], b[2][4];
#pragma unroll
            for (int mt = 0; mt < 4; mt++)
                ldm_x4(a[mt][0], a[mt][1], a[mt][2], a[mt][3],
                       Ab + mt * (16 * 144) + kk);
#pragma unroll
            for (int ng = 0; ng < 2; ng++)
                ldm_x4(b[ng][0], b[ng][1], b[ng][2], b[ng][3],
                       Bb + ng * (16 * 144) + kk);
#pragma unroll
            for (int mt = 0; mt < 4; mt++)
#pragma unroll
                for (int nt = 0; nt < 4; nt++)
                    mma_f16(acc[mt][nt],
                            a[mt][0], a[mt][1], a[mt][2], a[mt][3],
                            b[nt >> 1][(nt & 1) * 2], b[nt >> 1][(nt & 1) * 2 + 1]);
        }
        bufc = bnew;
    }

    // epilogue (fp16 out)
    const int grp = lane >> 2, tig = lane & 3;
#pragma unroll
    for (int mt = 0; mt < 4; mt++) {
        int r = row0 + wm * 64 + mt * 16 + grp;
#pragma unroll
        for (int nt = 0; nt < 4; nt++) {
            int col = col0 + wn * 32 + nt * 8 + tig * 2;
            float b0 = p.bias[col], b1 = p.bias[col + 1];
            __half2 lo, hi;
            lo.x = __float2half(acc[mt][nt][0] + b0);
            lo.y = __float2half(acc[mt][nt][1] + b1);
            hi.x = __float2half(acc[mt][nt][2] + b0);
            hi.y = __float2half(acc[mt][nt][3] + b1);
            *(__half2*)(p.C + (size_t)r * p.ldc + col) = lo;
            *(__half2*)(p.C + (size_t)(r + 8) * p.ldc + col) = hi;
        }
    }
}

struct B9 { const float* b[9]; };

// z = m*3 + t  (q/k/v of same modality adjacent: A stays L2-hot)
__global__ void __launch_bounds__(256, 2) qkv_gemm_kernel(B9 biases)
{
    const int colA[3] = {0, 2048, 2560};
    const int Kp[3]   = {2048, 512, 448};
    int z = blockIdx.z, m = z / 3, t = z - m * 3;
    GP p;
    p.Ah = g_ah; p.ldA = APAD; p.colA = colA[m];
    p.B  = g_wh + (size_t)t * 256 * APAD;
    p.ldB = APAD; p.colB = colA[m];
    p.Kp = Kp[m];
    p.bias = biases.b[t * 3 + m];
    p.C = ((t == 0) ? g_qh : (t == 1) ? g_kh : g_vh) + m * 256;
    p.ldc = QKV_LD;
    gemm_body(p);
}

__global__ void __launch_bounds__(256, 2) fc_gemm_kernel(const float* fc_b)
{
    GP p;
    p.Ah = g_oh; p.ldA = 256; p.colA = 0;
    p.B  = g_fch; p.ldB = 256; p.colB = 0;
    p.Kp = 256;
    p.bias = fc_b; p.C = g_fco; p.ldc = 256;
    gemm_body(p);
}

// ------------- fused attention: logits + L1 + softmax + PV --------------------
// KEY IDENTITY: (a/G)/max(sum|a/G|,1e-12) == a/sum|a|  (global-min G cancels),
// so no global reduction is needed. One thread per (sample, head).
__global__ void __launch_bounds__(256) attn_fused_kernel()
{
    int t  = blockIdx.x * blockDim.x + threadIdx.x;
    int bs = t >> 3, h = t & 7;
    const uint4* qb = (const uint4*)g_qh + (size_t)bs * 96 + h * 4;
    const uint4* kb = (const uint4*)g_kh + (size_t)bs * 96 + h * 4;
    const uint4* vb = (const uint4*)g_vh + (size_t)bs * 96 + h * 4;
    uint4* ob = (uint4*)g_oh + (size_t)bs * 96 + h * 4;

    // phase 1: probabilities p[m][n]
    uint4 kr[3][4];
#pragma unroll
    for (int n = 0; n < 3; n++)
#pragma unroll
        for (int j = 0; j < 4; j++) kr[n][j] = kb[n * 32 + j];

    float p[3][3];
#pragma unroll
    for (int m = 0; m < 3; m++) {
        uint4 qv[4];
#pragma unroll
        for (int j = 0; j < 4; j++) qv[j] = qb[m * 32 + j];
        float a[3];
#pragma unroll
        for (int n = 0; n < 3; n++) {
            float s = 0.f;
#pragma unroll
            for (int j = 0; j < 4; j++) s += dot8(qv[j], kr[n][j]);
            a[n] = s * TEMP_INV;
        }
        float l1 = fmaxf(fabsf(a[0]) + fabsf(a[1]) + fabsf(a[2]), 1e-30f);
        float r0 = a[0]/l1, r1 = a[1]/l1, r2 = a[2]/l1;
        float mx = fmaxf(r0, fmaxf(r1, r2));
        float e0 = expf(r0-mx), e1 = expf(r1-mx), e2 = expf(r2-mx);
        float es = e0 + e1 + e2;
        p[m][0] = e0/es; p[m][1] = e1/es; p[m][2] = e2/es;
    }

    // phase 2: PV, j-chunked (v loaded once per j, reused for all 3 m)
#pragma unroll
    for (int j = 0; j < 4; j++) {
        uint4 v0 = vb[j], v1 = vb[32 + j], v2 = vb[64 + j];
        const __half2* a0 = (const __half2*)&v0;
        const __half2* a1 = (const __half2*)&v1;
        const __half2* a2 = (const __half2*)&v2;
#pragma unroll
        for (int m = 0; m < 3; m++) {
            uint4 o;
            __half2* oh = (__half2*)&o;
#pragma unroll
            for (int i = 0; i < 4; i++) {
                float2 f0 = __half22float2(a0[i]);
                float2 f1 = __half22float2(a1[i]);
                float2 f2 = __half22float2(a2[i]);
                __half2 r;
                r.x = __float2half(p[m][0]*f0.x + p[m][1]*f1.x + p[m][2]*f2.x);
                r.y = __float2half(p[m][0]*f0.y + p[m][1]*f1.y + p[m][2]*f2.y);
                oh[i] = r;
            }
            ob[m * 32 + j] = o;
        }
    }
}

// ------------- fused residual + layernorm + out GEMM --------------------------
__global__ void __launch_bounds__(256) ln_out_kernel(
    const float* __restrict__ ln_g, const float* __restrict__ ln_b,
    const float* __restrict__ out_w, const float* __restrict__ out_b,
    float* __restrict__ out)
{
    __shared__ float red[8][8];
    __shared__ float bcast[8];

    int s = blockIdx.x, tid = threadIdx.x;
    int lane = tid & 31, wid = tid >> 5;

    float x[3];
#pragma unroll
    for (int m = 0; m < 3; m++) {
        size_t r = (size_t)(s * 3 + m) * 256 + tid;
        x[m] = __half2float(g_fco[r]) + __half2float(g_vh[r]);
    }

    float v6[6] = {x[0], x[1], x[2], x[0]*x[0], x[1]*x[1], x[2]*x[2]};
#pragma unroll
    for (int off = 16; off; off >>= 1)
#pragma unroll
        for (int i = 0; i < 6; i++)
            v6[i] += __shfl_xor_sync(0xFFFFFFFFu, v6[i], off);
    if (lane < 6) red[wid][lane] = v6[lane];
    __syncthreads();
    if (wid == 0) {
#pragma unroll
        for (int i = 0; i < 6; i++) {
            float t = (lane < 8) ? red[lane][i] : 0.f;
#pragma unroll
            for (int off = 4; off; off >>= 1)
                t += __shfl_xor_sync(0xFFFFFFFFu, t, off);
            if (lane == 0) bcast[i] = t;
        }
    }
    __syncthreads();

    float gg = ln_g[tid], bb = ln_b[tid];
    float acc[5] = {0.f, 0.f, 0.f, 0.f, 0.f};
#pragma unroll
    for (int m = 0; m < 3; m++) {
        float mu  = bcast[m] * (1.0f / 256.0f);
        float var = bcast[m + 3] * (1.0f / 256.0f) - mu * mu;
        float rstd = rsqrtf(var + LN_EPS);
        float xn = (x[m] - mu) * rstd * gg + bb;
        const float* wrow = out_w + (size_t)(m * 256 + tid) * 5;
#pragma unroll
        for (int c = 0; c < 5; c++) acc[c] = fmaf(xn, wrow[c], acc[c]);
    }
#pragma unroll
    for (int off = 16; off; off >>= 1)
#pragma unroll
        for (int c = 0; c < 5; c++)
            acc[c] += __shfl_xor_sync(0xFFFFFFFFu, acc[c], off);
    if (lane < 5) red[wid][lane] = acc[lane];
    __syncthreads();
    if (wid == 0 && lane < 5) {
        float t = 0.f;
#pragma unroll
        for (int w = 0; w < 8; w++) t += red[w][lane];
        out[s * 5 + lane] = t + out_b[lane];
    }
}

// ==============================================================================
extern "C" void kernel_launch(void* const* d_in, const int* in_sizes, int n_in,
                              void* d_out, int out_size)
{
    const float* X = (const float*)d_in[0];
    W9 ws; B9 bs;
    for (int t = 0; t < 3; t++)
        for (int m = 0; m < 3; m++) {
            ws.w[t*3+m] = (const float*)d_in[1 + t*6 + m*2];
            bs.b[t*3+m] = (const float*)d_in[2 + t*6 + m*2];
        }
    const float* fc_w  = (const float*)d_in[19];
    const float* fc_b  = (const float*)d_in[20];
    const float* ln_g  = (const float*)d_in[21];
    const float* ln_b  = (const float*)d_in[22];
    const float* out_w = (const float*)d_in[23];
    const float* out_b = (const float*)d_in[24];
    float* out = (float*)d_out;

    static int smem_set = 0;
    if (!smem_set) {
        cudaFuncSetAttribute(qkv_gemm_kernel, cudaFuncAttributeMaxDynamicSharedMemorySize, SMEM_GEMM);
        cudaFuncSetAttribute(fc_gemm_kernel,  cudaFuncAttributeMaxDynamicSharedMemorySize, SMEM_GEMM);
        smem_set = 1;
    }

    conv_x_kernel<<<dim3(3, BSZ), 256>>>(X);        // idx 0
    conv_w_kernel<<<dim3(1024, 1, 9), 256>>>(ws);   // idx 1
    conv_fcw_kernel<<<128, 256>>>(fc_w);            // idx 2

    qkv_gemm_kernel<<<dim3(2, BSZ/128, 9), 256, SMEM_GEMM>>>(bs);  // idx 3 -> ncu target

    attn_fused_kernel<<<(BSZ*8)/256, 256>>>();

    fc_gemm_kernel<<<dim3(2, NROWS/128, 1), 256, SMEM_GEMM>>>(fc_b);

    ln_out_kernel<<<BSZ, 256>>>(ln_g, ln_b, out_w, out_b, out);
}

// round 15
// speedup vs baseline: 1.5674x; 1.0725x over previous
#include <cuda_runtime.h>
#include <cuda_fp16.h>
#include <cstdint>

#define BSZ    16384
#define QKV_LD 768
#define NROWS  (BSZ*3)
#define LN_EPS 1e-6f
#define TEMP_INV 0.17677669529663687f
#define APAD   3072      // A layout stride; used cols = 2048+512+448 = 3008

// ---------------- scratch (static device arrays; no cudaMalloc) --------------
__device__ __align__(16) __half g_qh [BSZ*QKV_LD];
__device__ __align__(16) __half g_kh [BSZ*QKV_LD];
__device__ __align__(16) __half g_vh [BSZ*QKV_LD];
__device__ __align__(16) __half g_fco[BSZ*QKV_LD];
__device__ __align__(16) __half g_ah[(size_t)BSZ*APAD];
__device__ __align__(16) __half g_wh[(size_t)3*256*APAD];
__device__ __align__(16) __half g_oh[(size_t)NROWS*256];
__device__ __align__(16) __half g_fch[256*256];

// ---------------- small helpers ----------------------------------------------
__device__ __forceinline__ uint32_t su32(const void* p) {
    return (uint32_t)__cvta_generic_to_shared(p);
}
__device__ __forceinline__ void cp16(uint32_t dst, const void* src) {
    asm volatile("cp.async.cg.shared.global [%0], [%1], 16;"
                 :: "r"(dst), "l"(src) : "memory");
}
__device__ __forceinline__ void cp_commit() {
    asm volatile("cp.async.commit_group;" ::: "memory");
}
__device__ __forceinline__ void ldm_x4(uint32_t& r0, uint32_t& r1, uint32_t& r2,
                                       uint32_t& r3, uint32_t addr) {
    asm volatile("ldmatrix.sync.aligned.m8n8.x4.shared.b16 {%0,%1,%2,%3}, [%4];"
                 : "=r"(r0), "=r"(r1), "=r"(r2), "=r"(r3) : "r"(addr));
}
__device__ __forceinline__ void mma_f16(float* c, uint32_t a0, uint32_t a1,
                                        uint32_t a2, uint32_t a3,
                                        uint32_t b0, uint32_t b1) {
    asm volatile(
        "mma.sync.aligned.m16n8k16.row.col.f32.f16.f16.f32 "
        "{%0,%1,%2,%3}, {%4,%5,%6,%7}, {%8,%9}, {%0,%1,%2,%3};"
        : "+f"(c[0]), "+f"(c[1]), "+f"(c[2]), "+f"(c[3])
        : "r"(a0), "r"(a1), "r"(a2), "r"(a3), "r"(b0), "r"(b1));
}
__device__ __forceinline__ float dot8(uint4 a, uint4 b) {
    const __half2* pa = (const __half2*)&a;
    const __half2* pb = (const __half2*)&b;
    float s = 0.f;
#pragma unroll
    for (int i = 0; i < 4; i++) {
        float2 fa = __half22float2(pa[i]), fb = __half22float2(pb[i]);
        s = fmaf(fa.x, fb.x, s);
        s = fmaf(fa.y, fb.y, s);
    }
    return s;
}

// ---------------- conversion kernels -----------------------------------------
// padded segments: [0,2048) <- X[0,2000); [2048,2560) <- X[2000,2500); [2560,3008) <- X[2500,2900)
// 8 cols per thread (2x float4 loads, one 16B store) for MLP=2
__device__ __forceinline__ float4 load_seg(const float* __restrict__ X, int row, int col) {
    float4 v = make_float4(0.f, 0.f, 0.f, 0.f);
    if (col < 2048)      { if (col < 2000) v = *(const float4*)(X + (size_t)row*2900 + col); }
    else if (col < 2560) { int c = col-2048; if (c < 500) v = *(const float4*)(X + (size_t)row*2900 + 2000 + c); }
    else if (col < 3008) { int c = col-2560; if (c < 400) v = *(const float4*)(X + (size_t)row*2900 + 2500 + c); }
    return v;
}
__global__ void __launch_bounds__(256) conv_x_kernel(const float* __restrict__ X)
{
    int col = (blockIdx.x * 256 + threadIdx.x) * 8;
    if (col >= 3008) return;
    int row = blockIdx.y;

    float4 v0 = load_seg(X, row, col);
    float4 v1 = load_seg(X, row, col + 4);

    uint4 pk;
    __half2* ph = (__half2*)&pk;
    ph[0].x = __float2half(v0.x); ph[0].y = __float2half(v0.y);
    ph[1].x = __float2half(v0.z); ph[1].y = __float2half(v0.w);
    ph[2].x = __float2half(v1.x); ph[2].y = __float2half(v1.y);
    ph[3].x = __float2half(v1.z); ph[3].y = __float2half(v1.w);
    *(uint4*)&g_ah[(size_t)row*APAD + col] = pk;
}

struct W9 { const float* w[9]; };
__global__ void __launch_bounds__(256) conv_w_kernel(W9 ws)
{
    const int Km[3]   = {2000, 500, 400};
    const int Kp[3]   = {2048, 512, 448};
    const int colA[3] = {0, 2048, 2560};
    int z = blockIdx.z, t = z / 3, m = z - t * 3;
    int idx = (blockIdx.x * 256 + threadIdx.x) * 2;
    if (idx >= 256 * Kp[m]) return;
    int n  = idx / Kp[m];
    int kp = idx - n * Kp[m];
    const float* W = ws.w[z];
    float x0 = (kp     < Km[m]) ? W[(size_t)kp*256 + n]     : 0.f;
    float x1 = (kp + 1 < Km[m]) ? W[(size_t)(kp+1)*256 + n] : 0.f;
    __half2 hh; hh.x = __float2half(x0); hh.y = __float2half(x1);
    size_t o = (size_t)t*256*APAD + (size_t)n*APAD + colA[m] + kp;
    *(__half2*)&g_wh[o] = hh;
}

__global__ void __launch_bounds__(256) conv_fcw_kernel(const float* __restrict__ fcw)
{
    int idx = (blockIdx.x * 256 + threadIdx.x) * 2;
    int n = idx >> 8, k = idx & 255;
    __half2 hh;
    hh.x = __float2half(fcw[(size_t)k*256 + n]);
    hh.y = __float2half(fcw[(size_t)(k+1)*256 + n]);
    *(__half2*)&g_fch[n*256 + k] = hh;
}

// ---------------- mma.sync fp16 GEMM -------------------------------------------
// 256 threads, 8 warps (2x4), CTA tile 128x128, warp tile 64x32. Single product.
struct GP {
    const __half *Ah, *B;
    int ldA, ldB, colA, colB, Kp;
    const float* bias;
    __half* C; int ldc;
};

// stage: A 128x144B + B 128x144B  (K-chunk 64, 144B padded rows); 3 stages
#define SOFF_B 18432
#define SSTG   36864
#define NSTAGE 3
#define SMEM_GEMM (NSTAGE*SSTG)   // 110592 -> 2 CTAs/SM (216KB)

__device__ __forceinline__ void gemm_body(const GP p)
{
    extern __shared__ __align__(16) char dsm[];
    const int tid  = threadIdx.x;
    const int lane = tid & 31, wid = tid >> 5;
    const int wm = wid >> 2, wn = wid & 3;            // 2x4 warp grid
    const int row0 = blockIdx.y * 128, col0 = blockIdx.x * 128;
    const uint32_t sbase = su32(dsm);

    const int nchunk = p.Kp >> 6;      // K=64 chunks

    auto load_chunk = [&](int c, int buf) {
        const __half* As = p.Ah + (size_t)row0 * p.ldA + p.colA + c * 64;
        const __half* Bs = p.B  + (size_t)col0 * p.ldB + p.colB + c * 64;
        uint32_t Sd = sbase + buf * SSTG;
#pragma unroll
        for (int i = 0; i < 4; i++) {
            int id = i * 256 + tid, r = id >> 3, kg = id & 7;
            cp16(Sd + r * 144 + kg * 16, As + (size_t)r * p.ldA + kg * 8);
            cp16(Sd + SOFF_B + r * 144 + kg * 16, Bs + (size_t)r * p.ldB + kg * 8);
        }
    };

    float acc[4][4][4];
#pragma unroll
    for (int i = 0; i < 4; i++)
#pragma unroll
        for (int j = 0; j < 4; j++)
#pragma unroll
            for (int r = 0; r < 4; r++) acc[i][j][r] = 0.f;

    load_chunk(0, 0); cp_commit();

    const uint32_t a_off = (uint32_t)((wm * 64 + (lane & 15)) * 144 + ((lane >> 4) << 4));
    const uint32_t b_off = (uint32_t)((wn * 32 + (lane & 7) + ((lane & 16) >> 1)) * 144
                                      + ((lane & 8) << 1));

    int bufc = 0;
    for (int c = 0; c < nchunk; c++) {
        int bnew = bufc + 1; if (bnew == NSTAGE) bnew = 0;
        if (c + 1 < nchunk) {
            load_chunk(c + 1, bnew); cp_commit();
            asm volatile("cp.async.wait_group 1;" ::: "memory");
        } else {
            asm volatile("cp.async.wait_group 0;" ::: "memory");
        }
        __syncthreads();

        const uint32_t Sd = sbase + bufc * SSTG;
        const uint32_t Ab = Sd + a_off;
        const uint32_t Bb = Sd + SOFF_B + b_off;
#pragma unroll
        for (int kstep = 0; kstep < 4; kstep++) {
            const uint32_t kk = kstep * 32;
            uint32_t a[4][4], b[2][4];
#pragma unroll
            for (int mt = 0; mt < 4; mt++)
                ldm_x4(a[mt][0], a[mt][1], a[mt][2], a[mt][3],
                       Ab + mt * (16 * 144) + kk);
#pragma unroll
            for (int ng = 0; ng < 2; ng++)
                ldm_x4(b[ng][0], b[ng][1], b[ng][2], b[ng][3],
                       Bb + ng * (16 * 144) + kk);
#pragma unroll
            for (int mt = 0; mt < 4; mt++)
#pragma unroll
                for (int nt = 0; nt < 4; nt++)
                    mma_f16(acc[mt][nt],
                            a[mt][0], a[mt][1], a[mt][2], a[mt][3],
                            b[nt >> 1][(nt & 1) * 2], b[nt >> 1][(nt & 1) * 2 + 1]);
        }
        bufc = bnew;
    }

    // epilogue (fp16 out)
    const int grp = lane >> 2, tig = lane & 3;
#pragma unroll
    for (int mt = 0; mt < 4; mt++) {
        int r = row0 + wm * 64 + mt * 16 + grp;
#pragma unroll
        for (int nt = 0; nt < 4; nt++) {
            int col = col0 + wn * 32 + nt * 8 + tig * 2;
            float b0 = p.bias[col], b1 = p.bias[col + 1];
            __half2 lo, hi;
            lo.x = __float2half(acc[mt][nt][0] + b0);
            lo.y = __float2half(acc[mt][nt][1] + b1);
            hi.x = __float2half(acc[mt][nt][2] + b0);
            hi.y = __float2half(acc[mt][nt][3] + b1);
            *(__half2*)(p.C + (size_t)r * p.ldc + col) = lo;
            *(__half2*)(p.C + (size_t)(r + 8) * p.ldc + col) = hi;
        }
    }
}

struct B9 { const float* b[9]; };

// z = m*3 + t  (q/k/v of same modality adjacent: A stays L2-hot)
__global__ void __launch_bounds__(256, 2) qkv_gemm_kernel(B9 biases)
{
    const int colA[3] = {0, 2048, 2560};
    const int Kp[3]   = {2048, 512, 448};
    int z = blockIdx.z, m = z / 3, t = z - m * 3;
    GP p;
    p.Ah = g_ah; p.ldA = APAD; p.colA = colA[m];
    p.B  = g_wh + (size_t)t * 256 * APAD;
    p.ldB = APAD; p.colB = colA[m];
    p.Kp = Kp[m];
    p.bias = biases.b[t * 3 + m];
    p.C = ((t == 0) ? g_qh : (t == 1) ? g_kh : g_vh) + m * 256;
    p.ldc = QKV_LD;
    gemm_body(p);
}

__global__ void __launch_bounds__(256, 2) fc_gemm_kernel(const float* fc_b)
{
    GP p;
    p.Ah = g_oh; p.ldA = 256; p.colA = 0;
    p.B  = g_fch; p.ldB = 256; p.colB = 0;
    p.Kp = 256;
    p.bias = fc_b; p.C = g_fco; p.ldc = 256;
    gemm_body(p);
}

// ------------- fused attention: logits + L1 + softmax + PV --------------------
// Identity: (a/G)/max(sum|a/G|,1e-12) == a/sum|a|  (global-min G cancels).
__global__ void __launch_bounds__(256) attn_fused_kernel()
{
    int t  = blockIdx.x * blockDim.x + threadIdx.x;
    int bs = t >> 3, h = t & 7;
    const uint4* qb = (const uint4*)g_qh + (size_t)bs * 96 + h * 4;
    const uint4* kb = (const uint4*)g_kh + (size_t)bs * 96 + h * 4;
    const uint4* vb = (const uint4*)g_vh + (size_t)bs * 96 + h * 4;
    uint4* ob = (uint4*)g_oh + (size_t)bs * 96 + h * 4;

    uint4 kr[3][4];
#pragma unroll
    for (int n = 0; n < 3; n++)
#pragma unroll
        for (int j = 0; j < 4; j++) kr[n][j] = kb[n * 32 + j];

    float p[3][3];
#pragma unroll
    for (int m = 0; m < 3; m++) {
        uint4 qv[4];
#pragma unroll
        for (int j = 0; j < 4; j++) qv[j] = qb[m * 32 + j];
        float a[3];
#pragma unroll
        for (int n = 0; n < 3; n++) {
            float s = 0.f;
#pragma unroll
            for (int j = 0; j < 4; j++) s += dot8(qv[j], kr[n][j]);
            a[n] = s * TEMP_INV;
        }
        float l1 = fmaxf(fabsf(a[0]) + fabsf(a[1]) + fabsf(a[2]), 1e-30f);
        float r0 = a[0]/l1, r1 = a[1]/l1, r2 = a[2]/l1;
        float mx = fmaxf(r0, fmaxf(r1, r2));
        float e0 = expf(r0-mx), e1 = expf(r1-mx), e2 = expf(r2-mx);
        float es = e0 + e1 + e2;
        p[m][0] = e0/es; p[m][1] = e1/es; p[m][2] = e2/es;
    }

#pragma unroll
    for (int j = 0; j < 4; j++) {
        uint4 v0 = vb[j], v1 = vb[32 + j], v2 = vb[64 + j];
        const __half2* a0 = (const __half2*)&v0;
        const __half2* a1 = (const __half2*)&v1;
        const __half2* a2 = (const __half2*)&v2;
#pragma unroll
        for (int m = 0; m < 3; m++) {
            uint4 o;
            __half2* oh = (__half2*)&o;
#pragma unroll
            for (int i = 0; i < 4; i++) {
                float2 f0 = __half22float2(a0[i]);
                float2 f1 = __half22float2(a1[i]);
                float2 f2 = __half22float2(a2[i]);
                __half2 r;
                r.x = __float2half(p[m][0]*f0.x + p[m][1]*f1.x + p[m][2]*f2.x);
                r.y = __float2half(p[m][0]*f0.y + p[m][1]*f1.y + p[m][2]*f2.y);
                oh[i] = r;
            }
            ob[m * 32 + j] = o;
        }
    }
}

// ------------- fused residual + LN + out GEMM (8 samples/block, smem weights) --
__global__ void __launch_bounds__(256) ln_out_kernel(
    const float* __restrict__ ln_g, const float* __restrict__ ln_b,
    const float* __restrict__ out_w, const float* __restrict__ out_b,
    float* __restrict__ out)
{
    __shared__ float sw[768 * 5];      // 15360 B
    __shared__ float sg[256], sb[256];

    int tid = threadIdx.x;
    for (int i = tid; i < 768 * 5; i += 256) sw[i] = out_w[i];
    if (tid < 256) { sg[tid] = ln_g[tid]; sb[tid] = ln_b[tid]; }
    __syncthreads();

    int lane = tid & 31, wid = tid >> 5;
    int s = blockIdx.x * 8 + wid;      // one warp per sample

    // load x[m][i], col = i*32 + lane
    float x[3][8];
#pragma unroll
    for (int m = 0; m < 3; m++) {
        size_t base = (size_t)(s * 3 + m) * 256;
#pragma unroll
        for (int i = 0; i < 8; i++) {
            int col = i * 32 + lane;
            x[m][i] = __half2float(g_fco[base + col]) + __half2float(g_vh[base + col]);
        }
    }

    // per-row mean/var (warp-local)
    float mu[3], rstd[3];
#pragma unroll
    for (int m = 0; m < 3; m++) {
        float s1 = 0.f, s2 = 0.f;
#pragma unroll
        for (int i = 0; i < 8; i++) { s1 += x[m][i]; s2 = fmaf(x[m][i], x[m][i], s2); }
#pragma unroll
        for (int off = 16; off; off >>= 1) {
            s1 += __shfl_xor_sync(0xFFFFFFFFu, s1, off);
            s2 += __shfl_xor_sync(0xFFFFFFFFu, s2, off);
        }
        mu[m] = s1 * (1.0f / 256.0f);
        float var = s2 * (1.0f / 256.0f) - mu[m] * mu[m];
        rstd[m] = rsqrtf(var + LN_EPS);
    }

    // LN + dot with out_w (smem)
    float acc[5] = {0.f, 0.f, 0.f, 0.f, 0.f};
#pragma unroll
    for (int m = 0; m < 3; m++) {
#pragma unroll
        for (int i = 0; i < 8; i++) {
            int col = i * 32 + lane;
            float xn = (x[m][i] - mu[m]) * rstd[m] * sg[col] + sb[col];
            const float* wr = &sw[(m * 256 + col) * 5];
#pragma unroll
            for (int c = 0; c < 5; c++) acc[c] = fmaf(xn, wr[c], acc[c]);
        }
    }
#pragma unroll
    for (int off = 16; off; off >>= 1)
#pragma unroll
        for (int c = 0; c < 5; c++)
            acc[c] += __shfl_xor_sync(0xFFFFFFFFu, acc[c], off);
    if (lane < 5) out[s * 5 + lane] = acc[lane] + out_b[lane];
}

// ==============================================================================
extern "C" void kernel_launch(void* const* d_in, const int* in_sizes, int n_in,
                              void* d_out, int out_size)
{
    const float* X = (const float*)d_in[0];
    W9 ws; B9 bs;
    for (int t = 0; t < 3; t++)
        for (int m = 0; m < 3; m++) {
            ws.w[t*3+m] = (const float*)d_in[1 + t*6 + m*2];
            bs.b[t*3+m] = (const float*)d_in[2 + t*6 + m*2];
        }
    const float* fc_w  = (const float*)d_in[19];
    const float* fc_b  = (const float*)d_in[20];
    const float* ln_g  = (const float*)d_in[21];
    const float* ln_b  = (const float*)d_in[22];
    const float* out_w = (const float*)d_in[23];
    const float* out_b = (const float*)d_in[24];
    float* out = (float*)d_out;

    static int smem_set = 0;
    if (!smem_set) {
        cudaFuncSetAttribute(qkv_gemm_kernel, cudaFuncAttributeMaxDynamicSharedMemorySize, SMEM_GEMM);
        cudaFuncSetAttribute(fc_gemm_kernel,  cudaFuncAttributeMaxDynamicSharedMemorySize, SMEM_GEMM);
        smem_set = 1;
    }

    conv_x_kernel<<<dim3(2, BSZ), 256>>>(X);        // idx 0
    conv_w_kernel<<<dim3(1024, 1, 9), 256>>>(ws);   // idx 1
    conv_fcw_kernel<<<128, 256>>>(fc_w);            // idx 2

    qkv_gemm_kernel<<<dim3(2, BSZ/128, 9), 256, SMEM_GEMM>>>(bs);  // idx 3 -> ncu target

    attn_fused_kernel<<<(BSZ*8)/256, 256>>>();

    fc_gemm_kernel<<<dim3(2, NROWS/128, 1), 256, SMEM_GEMM>>>(fc_b);

    ln_out_kernel<<<BSZ/8, 256>>>(ln_g, ln_b, out_w, out_b, out);
}

// round 16
// speedup vs baseline: 1.6803x; 1.0720x over previous
#include <cuda_runtime.h>
#include <cuda_fp16.h>
#include <cstdint>

#define BSZ    16384
#define QKV_LD 768
#define NROWS  (BSZ*3)
#define LN_EPS 1e-6f
#define TEMP_INV 0.17677669529663687f
#define APAD   3072      // A layout stride; used cols = 2048+512+448 = 3008

// ---------------- scratch (static device arrays; no cudaMalloc) --------------
__device__ __align__(16) __half g_qh [BSZ*QKV_LD];
__device__ __align__(16) __half g_kh [BSZ*QKV_LD];
__device__ __align__(16) __half g_vh [BSZ*QKV_LD];
__device__ __align__(16) __half g_fco[BSZ*QKV_LD];
__device__ __align__(16) __half g_ah[(size_t)BSZ*APAD];
__device__ __align__(16) __half g_wh[(size_t)3*256*APAD];
__device__ __align__(16) __half g_oh[(size_t)NROWS*256];
__device__ __align__(16) __half g_fch[256*256];

// ---------------- small helpers ----------------------------------------------
__device__ __forceinline__ uint32_t su32(const void* p) {
    return (uint32_t)__cvta_generic_to_shared(p);
}
__device__ __forceinline__ void cp16(uint32_t dst, const void* src) {
    asm volatile("cp.async.cg.shared.global [%0], [%1], 16;"
                 :: "r"(dst), "l"(src) : "memory");
}
__device__ __forceinline__ void cp_commit() {
    asm volatile("cp.async.commit_group;" ::: "memory");
}
__device__ __forceinline__ void ldm_x4(uint32_t& r0, uint32_t& r1, uint32_t& r2,
                                       uint32_t& r3, uint32_t addr) {
    asm volatile("ldmatrix.sync.aligned.m8n8.x4.shared.b16 {%0,%1,%2,%3}, [%4];"
                 : "=r"(r0), "=r"(r1), "=r"(r2), "=r"(r3) : "r"(addr));
}
__device__ __forceinline__ void mma_f16(float* c, uint32_t a0, uint32_t a1,
                                        uint32_t a2, uint32_t a3,
                                        uint32_t b0, uint32_t b1) {
    asm volatile(
        "mma.sync.aligned.m16n8k16.row.col.f32.f16.f16.f32 "
        "{%0,%1,%2,%3}, {%4,%5,%6,%7}, {%8,%9}, {%0,%1,%2,%3};"
        : "+f"(c[0]), "+f"(c[1]), "+f"(c[2]), "+f"(c[3])
        : "r"(a0), "r"(a1), "r"(a2), "r"(a3), "r"(b0), "r"(b1));
}
__device__ __forceinline__ float dot8(uint4 a, uint4 b) {
    const __half2* pa = (const __half2*)&a;
    const __half2* pb = (const __half2*)&b;
    float s = 0.f;
#pragma unroll
    for (int i = 0; i < 4; i++) {
        float2 fa = __half22float2(pa[i]), fb = __half22float2(pb[i]);
        s = fmaf(fa.x, fb.x, s);
        s = fmaf(fa.y, fb.y, s);
    }
    return s;
}

// ---------------- conv_x: X fp32 -> padded fp16 A ------------------------------
// segments: [0,2048)<-X[0,2000); [2048,2560)<-X[2000,2500); [2560,3008)<-X[2500,2900)
__device__ __forceinline__ float4 load_seg(const float* __restrict__ X, int row, int col) {
    float4 v = make_float4(0.f, 0.f, 0.f, 0.f);
    if (col < 2048)      { if (col < 2000) v = *(const float4*)(X + (size_t)row*2900 + col); }
    else if (col < 2560) { int c = col-2048; if (c < 500) v = *(const float4*)(X + (size_t)row*2900 + 2000 + c); }
    else if (col < 3008) { int c = col-2560; if (c < 400) v = *(const float4*)(X + (size_t)row*2900 + 2500 + c); }
    return v;
}
__global__ void __launch_bounds__(256) conv_x_kernel(const float* __restrict__ X)
{
    int col = (blockIdx.x * 256 + threadIdx.x) * 8;
    if (col >= 3008) return;
    int row = blockIdx.y;

    float4 v0 = load_seg(X, row, col);
    float4 v1 = load_seg(X, row, col + 4);

    uint4 pk;
    __half2* ph = (__half2*)&pk;
    ph[0].x = __float2half(v0.x); ph[0].y = __float2half(v0.y);
    ph[1].x = __float2half(v0.z); ph[1].y = __float2half(v0.w);
    ph[2].x = __float2half(v1.x); ph[2].y = __float2half(v1.y);
    ph[3].x = __float2half(v1.z); ph[3].y = __float2half(v1.w);
    *(uint4*)&g_ah[(size_t)row*APAD + col] = pk;
}

// ---------------- conv_wt: tiled transpose of all weights ----------------------
// 10 segments: s=t*3+m -> w[s]: [Km,256] fp32 -> g_wh[t*256*APAD + n*APAD + colA[m] + kp] fp16
//              s=9     -> fc_w: [256,256] fp32 -> g_fch[n*256 + k] fp16
// 64x64 tiles; coalesced reads (rows of W), smem transpose, coalesced half2 writes.
#define NWT_BLOCKS 580    // 3*(128+32+28) + 16
struct WA { const float* w[9]; const float* fcw; };

__global__ void __launch_bounds__(256) conv_wt_kernel(WA a)
{
    const int KpT[10]  = {2048,512,448, 2048,512,448, 2048,512,448, 256};
    const int KmT[10]  = {2000,500,400, 2000,500,400, 2000,500,400, 256};
    const int offT[10] = {0,2048,2560, 0,2048,2560, 0,2048,2560, 0};

    int b = blockIdx.x;
    int seg = 0, base = 0;
#pragma unroll
    for (int s = 0; s < 10; s++) {
        int nt = KpT[s] >> 4;          // (Kp/64)*(256/64)
        if (b < base + nt) { seg = s; break; }
        base += nt;
    }
    int lt = b - base;
    int ktiles = KpT[seg] >> 6;
    int kp0 = (lt % ktiles) * 64;
    int n0  = (lt / ktiles) * 64;
    int Km  = KmT[seg];
    const float* W = (seg < 9) ? a.w[seg] : a.fcw;
    __half* dst; int ld, coff;
    if (seg < 9) { dst = g_wh + (size_t)(seg / 3) * 256 * APAD; ld = APAD; coff = offT[seg]; }
    else         { dst = g_fch; ld = 256; coff = 0; }

    __shared__ float s[64][65];
    int tid = threadIdx.x;
    int c = tid & 63, r0 = tid >> 6;   // 4 rows per pass
#pragma unroll
    for (int i = 0; i < 16; i++) {
        int r = r0 + i * 4;
        int kp = kp0 + r;
        s[r][c] = (kp < Km) ? W[(size_t)kp * 256 + n0 + c] : 0.f;
    }
    __syncthreads();

    int kl = (tid & 31) * 2;
#pragma unroll
    for (int j = 0; j < 8; j++) {
        int nl = (tid >> 5) + j * 8;
        __half2 h;
        h.x = __float2half(s[kl][nl]);
        h.y = __float2half(s[kl + 1][nl]);
        *(__half2*)&dst[(size_t)(n0 + nl) * ld + coff + kp0 + kl] = h;
    }
}

// ---------------- mma.sync fp16 GEMM -------------------------------------------
// 256 threads, 8 warps (2x4), CTA tile 128x128, warp tile 64x32. Single product.
struct GP {
    const __half *Ah, *B;
    int ldA, ldB, colA, colB, Kp;
    const float* bias;
    __half* C; int ldc;
};

#define SOFF_B 18432
#define SSTG   36864
#define NSTAGE 3
#define SMEM_GEMM (NSTAGE*SSTG)   // 110592 -> 2 CTAs/SM (216KB)

__device__ __forceinline__ void gemm_body(const GP p)
{
    extern __shared__ __align__(16) char dsm[];
    const int tid  = threadIdx.x;
    const int lane = tid & 31, wid = tid >> 5;
    const int wm = wid >> 2, wn = wid & 3;            // 2x4 warp grid
    const int row0 = blockIdx.y * 128, col0 = blockIdx.x * 128;
    const uint32_t sbase = su32(dsm);

    const int nchunk = p.Kp >> 6;      // K=64 chunks

    auto load_chunk = [&](int c, int buf) {
        const __half* As = p.Ah + (size_t)row0 * p.ldA + p.colA + c * 64;
        const __half* Bs = p.B  + (size_t)col0 * p.ldB + p.colB + c * 64;
        uint32_t Sd = sbase + buf * SSTG;
#pragma unroll
        for (int i = 0; i < 4; i++) {
            int id = i * 256 + tid, r = id >> 3, kg = id & 7;
            cp16(Sd + r * 144 + kg * 16, As + (size_t)r * p.ldA + kg * 8);
            cp16(Sd + SOFF_B + r * 144 + kg * 16, Bs + (size_t)r * p.ldB + kg * 8);
        }
    };

    float acc[4][4][4];
#pragma unroll
    for (int i = 0; i < 4; i++)
#pragma unroll
        for (int j = 0; j < 4; j++)
#pragma unroll
            for (int r = 0; r < 4; r++) acc[i][j][r] = 0.f;

    load_chunk(0, 0); cp_commit();

    const uint32_t a_off = (uint32_t)((wm * 64 + (lane & 15)) * 144 + ((lane >> 4) << 4));
    const uint32_t b_off = (uint32_t)((wn * 32 + (lane & 7) + ((lane & 16) >> 1)) * 144
                                      + ((lane & 8) << 1));

    int bufc = 0;
    for (int c = 0; c < nchunk; c++) {
        int bnew = bufc + 1; if (bnew == NSTAGE) bnew = 0;
        if (c + 1 < nchunk) {
            load_chunk(c + 1, bnew); cp_commit();
            asm volatile("cp.async.wait_group 1;" ::: "memory");
        } else {
            asm volatile("cp.async.wait_group 0;" ::: "memory");
        }
        __syncthreads();

        const uint32_t Sd = sbase + bufc * SSTG;
        const uint32_t Ab = Sd + a_off;
        const uint32_t Bb = Sd + SOFF_B + b_off;
#pragma unroll
        for (int kstep = 0; kstep < 4; kstep++) {
            const uint32_t kk = kstep * 32;
            uint32_t a[4][4], b[2][4];
#pragma unroll
            for (int mt = 0; mt < 4; mt++)
                ldm_x4(a[mt][0], a[mt][1], a[mt][2], a[mt][3],
                       Ab + mt * (16 * 144) + kk);
#pragma unroll
            for (int ng = 0; ng < 2; ng++)
                ldm_x4(b[ng][0], b[ng][1], b[ng][2], b[ng][3],
                       Bb + ng * (16 * 144) + kk);
#pragma unroll
            for (int mt = 0; mt < 4; mt++)
#pragma unroll
                for (int nt = 0; nt < 4; nt++)
                    mma_f16(acc[mt][nt],
                            a[mt][0], a[mt][1], a[mt][2], a[mt][3],
                            b[nt >> 1][(nt & 1) * 2], b[nt >> 1][(nt & 1) * 2 + 1]);
        }
        bufc = bnew;
    }

    // epilogue (fp16 out)
    const int grp = lane >> 2, tig = lane & 3;
#pragma unroll
    for (int mt = 0; mt < 4; mt++) {
        int r = row0 + wm * 64 + mt * 16 + grp;
#pragma unroll
        for (int nt = 0; nt < 4; nt++) {
            int col = col0 + wn * 32 + nt * 8 + tig * 2;
            float b0 = p.bias[col], b1 = p.bias[col + 1];
            __half2 lo, hi;
            lo.x = __float2half(acc[mt][nt][0] + b0);
            lo.y = __float2half(acc[mt][nt][1] + b1);
            hi.x = __float2half(acc[mt][nt][2] + b0);
            hi.y = __float2half(acc[mt][nt][3] + b1);
            *(__half2*)(p.C + (size_t)r * p.ldc + col) = lo;
            *(__half2*)(p.C + (size_t)(r + 8) * p.ldc + col) = hi;
        }
    }
}

struct B9 { const float* b[9]; };

// z = m*3 + t  (q/k/v of same modality adjacent: A stays L2-hot)
__global__ void __launch_bounds__(256, 2) qkv_gemm_kernel(B9 biases)
{
    const int colA[3] = {0, 2048, 2560};
    const int Kp[3]   = {2048, 512, 448};
    int z = blockIdx.z, m = z / 3, t = z - m * 3;
    GP p;
    p.Ah = g_ah; p.ldA = APAD; p.colA = colA[m];
    p.B  = g_wh + (size_t)t * 256 * APAD;
    p.ldB = APAD; p.colB = colA[m];
    p.Kp = Kp[m];
    p.bias = biases.b[t * 3 + m];
    p.C = ((t == 0) ? g_qh : (t == 1) ? g_kh : g_vh) + m * 256;
    p.ldc = QKV_LD;
    gemm_body(p);
}

__global__ void __launch_bounds__(256, 2) fc_gemm_kernel(const float* fc_b)
{
    GP p;
    p.Ah = g_oh; p.ldA = 256; p.colA = 0;
    p.B  = g_fch; p.ldB = 256; p.colB = 0;
    p.Kp = 256;
    p.bias = fc_b; p.C = g_fco; p.ldc = 256;
    gemm_body(p);
}

// ------------- fused attention: logits + L1 + softmax + PV --------------------
// Identity: (a/G)/max(sum|a/G|,1e-12) == a/sum|a|  (global-min G cancels).
__global__ void __launch_bounds__(256) attn_fused_kernel()
{
    int t  = blockIdx.x * blockDim.x + threadIdx.x;
    int bs = t >> 3, h = t & 7;
    const uint4* qb = (const uint4*)g_qh + (size_t)bs * 96 + h * 4;
    const uint4* kb = (const uint4*)g_kh + (size_t)bs * 96 + h * 4;
    const uint4* vb = (const uint4*)g_vh + (size_t)bs * 96 + h * 4;
    uint4* ob = (uint4*)g_oh + (size_t)bs * 96 + h * 4;

    uint4 kr[3][4];
#pragma unroll
    for (int n = 0; n < 3; n++)
#pragma unroll
        for (int j = 0; j < 4; j++) kr[n][j] = kb[n * 32 + j];

    float p[3][3];
#pragma unroll
    for (int m = 0; m < 3; m++) {
        uint4 qv[4];
#pragma unroll
        for (int j = 0; j < 4; j++) qv[j] = qb[m * 32 + j];
        float a[3];
#pragma unroll
        for (int n = 0; n < 3; n++) {
            float s = 0.f;
#pragma unroll
            for (int j = 0; j < 4; j++) s += dot8(qv[j], kr[n][j]);
            a[n] = s * TEMP_INV;
        }
        float l1 = fmaxf(fabsf(a[0]) + fabsf(a[1]) + fabsf(a[2]), 1e-30f);
        float r0 = a[0]/l1, r1 = a[1]/l1, r2 = a[2]/l1;
        float mx = fmaxf(r0, fmaxf(r1, r2));
        float e0 = expf(r0-mx), e1 = expf(r1-mx), e2 = expf(r2-mx);
        float es = e0 + e1 + e2;
        p[m][0] = e0/es; p[m][1] = e1/es; p[m][2] = e2/es;
    }

#pragma unroll
    for (int j = 0; j < 4; j++) {
        uint4 v0 = vb[j], v1 = vb[32 + j], v2 = vb[64 + j];
        const __half2* a0 = (const __half2*)&v0;
        const __half2* a1 = (const __half2*)&v1;
        const __half2* a2 = (const __half2*)&v2;
#pragma unroll
        for (int m = 0; m < 3; m++) {
            uint4 o;
            __half2* oh = (__half2*)&o;
#pragma unroll
            for (int i = 0; i < 4; i++) {
                float2 f0 = __half22float2(a0[i]);
                float2 f1 = __half22float2(a1[i]);
                float2 f2 = __half22float2(a2[i]);
                __half2 r;
                r.x = __float2half(p[m][0]*f0.x + p[m][1]*f1.x + p[m][2]*f2.x);
                r.y = __float2half(p[m][0]*f0.y + p[m][1]*f1.y + p[m][2]*f2.y);
                oh[i] = r;
            }
            ob[m * 32 + j] = o;
        }
    }
}

// ------------- fused residual + LN + out GEMM (8 samples/block, smem weights) --
__global__ void __launch_bounds__(256) ln_out_kernel(
    const float* __restrict__ ln_g, const float* __restrict__ ln_b,
    const float* __restrict__ out_w, const float* __restrict__ out_b,
    float* __restrict__ out)
{
    __shared__ float sw[768 * 5];
    __shared__ float sg[256], sb[256];

    int tid = threadIdx.x;
    for (int i = tid; i < 768 * 5; i += 256) sw[i] = out_w[i];
    if (tid < 256) { sg[tid] = ln_g[tid]; sb[tid] = ln_b[tid]; }
    __syncthreads();

    int lane = tid & 31, wid = tid >> 5;
    int s = blockIdx.x * 8 + wid;

    float x[3][8];
#pragma unroll
    for (int m = 0; m < 3; m++) {
        size_t base = (size_t)(s * 3 + m) * 256;
#pragma unroll
        for (int i = 0; i < 8; i++) {
            int col = i * 32 + lane;
            x[m][i] = __half2float(g_fco[base + col]) + __half2float(g_vh[base + col]);
        }
    }

    float mu[3], rstd[3];
#pragma unroll
    for (int m = 0; m < 3; m++) {
        float s1 = 0.f, s2 = 0.f;
#pragma unroll
        for (int i = 0; i < 8; i++) { s1 += x[m][i]; s2 = fmaf(x[m][i], x[m][i], s2); }
#pragma unroll
        for (int off = 16; off; off >>= 1) {
            s1 += __shfl_xor_sync(0xFFFFFFFFu, s1, off);
            s2 += __shfl_xor_sync(0xFFFFFFFFu, s2, off);
        }
        mu[m] = s1 * (1.0f / 256.0f);
        float var = s2 * (1.0f / 256.0f) - mu[m] * mu[m];
        rstd[m] = rsqrtf(var + LN_EPS);
    }

    float acc[5] = {0.f, 0.f, 0.f, 0.f, 0.f};
#pragma unroll
    for (int m = 0; m < 3; m++) {
#pragma unroll
        for (int i = 0; i < 8; i++) {
            int col = i * 32 + lane;
            float xn = (x[m][i] - mu[m]) * rstd[m] * sg[col] + sb[col];
            const float* wr = &sw[(m * 256 + col) * 5];
#pragma unroll
            for (int c = 0; c < 5; c++) acc[c] = fmaf(xn, wr[c], acc[c]);
        }
    }
#pragma unroll
    for (int off = 16; off; off >>= 1)
#pragma unroll
        for (int c = 0; c < 5; c++)
            acc[c] += __shfl_xor_sync(0xFFFFFFFFu, acc[c], off);
    if (lane < 5) out[s * 5 + lane] = acc[lane] + out_b[lane];
}

// ==============================================================================
extern "C" void kernel_launch(void* const* d_in, const int* in_sizes, int n_in,
                              void* d_out, int out_size)
{
    const float* X = (const float*)d_in[0];
    WA wa; B9 bs;
    for (int t = 0; t < 3; t++)
        for (int m = 0; m < 3; m++) {
            wa.w[t*3+m] = (const float*)d_in[1 + t*6 + m*2];
            bs.b[t*3+m] = (const float*)d_in[2 + t*6 + m*2];
        }
    wa.fcw = (const float*)d_in[19];
    const float* fc_b  = (const float*)d_in[20];
    const float* ln_g  = (const float*)d_in[21];
    const float* ln_b  = (const float*)d_in[22];
    const float* out_w = (const float*)d_in[23];
    const float* out_b = (const float*)d_in[24];
    float* out = (float*)d_out;

    static int smem_set = 0;
    if (!smem_set) {
        cudaFuncSetAttribute(qkv_gemm_kernel, cudaFuncAttributeMaxDynamicSharedMemorySize, SMEM_GEMM);
        cudaFuncSetAttribute(fc_gemm_kernel,  cudaFuncAttributeMaxDynamicSharedMemorySize, SMEM_GEMM);
        smem_set = 1;
    }

    conv_x_kernel<<<dim3(2, BSZ), 256>>>(X);        // idx 0
    conv_wt_kernel<<<NWT_BLOCKS, 256>>>(wa);        // idx 1

    qkv_gemm_kernel<<<dim3(2, BSZ/128, 9), 256, SMEM_GEMM>>>(bs);  // idx 2

    attn_fused_kernel<<<(BSZ*8)/256, 256>>>();      // idx 3 -> ncu target

    fc_gemm_kernel<<<dim3(2, NROWS/128, 1), 256, SMEM_GEMM>>>(fc_b);

    ln_out_kernel<<<BSZ/8, 256>>>(ln_g, ln_b, out_w, out_b, out);
}